// round 14
// baseline (speedup 1.0000x reference)
#include <cuda_runtime.h>
#include <cuda_fp16.h>
#include <math.h>
#include <stdint.h>

#define Nn 65536
#define Ee 1048576
#define Bb 64
#define Hh 128

// ------------------- scratch (static device globals) -------------------
__device__ float g_csum[Bb * 4];
__device__ float g_center[Bb * 3];
__device__ float g_posrel[Nn * 3];
__device__ float g_x0[Nn * Hh];
__device__ uint32_t g_xhi[Nn * 64];       // fp16x2-packed hi split of x
__device__ uint32_t g_xlo[Nn * 64];       // fp16x2-packed lo split (residual)
__device__ float g_xa[Nn * Hh];
__device__ float g_xb[Nn * Hh];
__device__ float g_msum[Nn * Hh];
__device__ int   g_deg[Nn];
__device__ float g_invdeg[Nn];
__device__ float g_gsum[Bb * Hh];
__device__ float g_ligcnt[Bb];
// edge sort scratch
__device__ int   g_rowstart[Nn];
__device__ int   g_rowcur[Nn];
__device__ int   g_blksum[256];
__device__ int   g_srow[Ee];
__device__ int   g_scol[Ee];
__device__ float g_sdist[Ee];
// fragment-linear weights (fp16x2 pairs per lane)
__device__ uint2 g_w1f[3 * 8192];   // W1^T 256n x 128k, NT=32
__device__ uint2 g_w2f[3 * 4096];   // W2^T 128n x 128k, NT=16
__device__ uint2 g_uf[3 * 8192];    // U^T  128n x 256k, NT=16
__device__ uint2 g_linf[4096];      // lin^T 128n x 128k, NT=16

// ------------------- helpers -------------------
__device__ __forceinline__ uint32_t smem_u32(const void* p) {
    uint32_t a;
    asm("{ .reg .u64 t; cvta.to.shared.u64 t, %1; cvt.u32.u64 %0, t; }" : "=r"(a) : "l"(p));
    return a;
}
__device__ __forceinline__ void ldsm_x4(uint32_t* r, uint32_t addr) {
    asm volatile("ldmatrix.sync.aligned.m8n8.x4.shared.b16 {%0,%1,%2,%3}, [%4];"
                 : "=r"(r[0]), "=r"(r[1]), "=r"(r[2]), "=r"(r[3]) : "r"(addr));
}
__device__ __forceinline__ void mma_f16(float* d, const uint32_t* a, const uint32_t* b) {
    asm volatile("mma.sync.aligned.m16n8k16.row.col.f32.f16.f16.f32 "
                 "{%0,%1,%2,%3}, {%4,%5,%6,%7}, {%8,%9}, {%0,%1,%2,%3};"
                 : "+f"(d[0]), "+f"(d[1]), "+f"(d[2]), "+f"(d[3])
                 : "r"(a[0]), "r"(a[1]), "r"(a[2]), "r"(a[3]), "r"(b[0]), "r"(b[1]));
}
__device__ __forceinline__ void split2(float v0, float v1, uint32_t& hi, uint32_t& lo) {
    __half2 h = __floats2half2_rn(v0, v1);
    float h0 = __half2float(__low2half(h));
    float h1 = __half2float(__high2half(h));
    __half2 l = __floats2half2_rn(v0 - h0, v1 - h1);
    hi = *(uint32_t*)&h;
    lo = *(uint32_t*)&l;
}
__device__ __forceinline__ uint32_t pack_h2(float v0, float v1) {
    __half2 h = __floats2half2_rn(v0, v1);
    return *(uint32_t*)&h;
}
// PDL primitives (sm_90+ PTX, no arch suffix)
__device__ __forceinline__ void gdc_launch_dependents() {
    asm volatile("griddepcontrol.launch_dependents;");
}
__device__ __forceinline__ void gdc_wait() {
    asm volatile("griddepcontrol.wait;" ::: "memory");
}

// 2-term MMA core, warp tile m16 x n64 (8 warp_m x 2 warp_n):
// A ldsm redundancy 2x (was 4x). D += (Ahi + Alo) * Bhi, B fragment-linear in global.
__device__ __forceinline__ void mma2_gf(uint32_t sbase, uint32_t oAhi, uint32_t oAlo,
                                        const uint2* __restrict__ bf,
                                        int NT, int nt_base, int ks_base,
                                        int lane, int warp_m,
                                        float (&acc)[8][4]) {
    uint32_t a_base = sbase + oAhi + (uint32_t)(warp_m * 16 + (lane & 15)) * 272 + (uint32_t)(lane >> 4) * 16;
    uint32_t dA = oAlo - oAhi;
    for (int ks = 0; ks < 8; ks++) {
        uint32_t kb = (uint32_t)ks * 32;
        uint32_t a_hi[4], a_lo[4];
        ldsm_x4(a_hi, a_base + kb);
        ldsm_x4(a_lo, a_base + dA + kb);
        int fks = (ks_base + ks) * NT + nt_base;
        #pragma unroll
        for (int nt = 0; nt < 8; nt++) {
            uint2 bh = __ldg(bf + (size_t)(fks + nt) * 32 + lane);
            uint32_t bhv[2] = {bh.x, bh.y};
            mma_f16(acc[nt], a_hi, bhv);
            mma_f16(acc[nt], a_lo, bhv);
        }
    }
}

__device__ __forceinline__ void stage_acc(char* sm, uint32_t oM, int lane, int warp_m, int warp_n,
                                          float (&acc)[8][4]) {
    int er = warp_m * 16 + (lane >> 2);
    #pragma unroll
    for (int nt = 0; nt < 8; nt++) {
        int cb = warp_n * 64 + nt * 8 + (lane & 3) * 2;
        *(float2*)(sm + oM + (uint32_t)er * 528 + cb * 4) = make_float2(acc[nt][0], acc[nt][1]);
        *(float2*)(sm + oM + (uint32_t)(er + 8) * 528 + cb * 4) = make_float2(acc[nt][2], acc[nt][3]);
    }
}

__device__ __forceinline__ void write_frag_out(float* out, int n0, int lane, int warp_m, int warp_n,
                                               const float* bsm, float (&acc)[8][4]) {
    int er = n0 + warp_m * 16 + (lane >> 2);
    #pragma unroll
    for (int nt = 0; nt < 8; nt++) {
        int cb = warp_n * 64 + nt * 8 + (lane & 3) * 2;
        float b0 = bsm ? bsm[cb] : 0.f;
        float b1 = bsm ? bsm[cb + 1] : 0.f;
        *(float2*)(out + (size_t)er * 128 + cb) = make_float2(acc[nt][0] + b0, acc[nt][1] + b1);
        *(float2*)(out + (size_t)(er + 8) * 128 + cb) = make_float2(acc[nt][2] + b0, acc[nt][3] + b1);
    }
}

#define ACC_ZERO(acc) \
    _Pragma("unroll") \
    for (int nt = 0; nt < 8; nt++) \
        _Pragma("unroll") \
        for (int q = 0; q < 4; q++) (acc)[nt][q] = 0.f;

// ------------------- small kernels -------------------
__global__ void k_center_sum(const float* __restrict__ pos, const int* __restrict__ batch) {
    int n = blockIdx.x * blockDim.x + threadIdx.x;
    if (n >= Nn) return;
    int lane = threadIdx.x & 31;
    int b = batch[n];
    float px = pos[n * 3 + 0], py = pos[n * 3 + 1], pz = pos[n * 3 + 2], pc = 1.f;
    #pragma unroll
    for (int off = 1; off < 32; off <<= 1) {
        int bs = __shfl_down_sync(0xffffffffu, b, off);
        float tx = __shfl_down_sync(0xffffffffu, px, off);
        float ty = __shfl_down_sync(0xffffffffu, py, off);
        float tz = __shfl_down_sync(0xffffffffu, pz, off);
        float tc = __shfl_down_sync(0xffffffffu, pc, off);
        if (lane + off < 32 && bs == b) { px += tx; py += ty; pz += tz; pc += tc; }
    }
    int bprev = __shfl_up_sync(0xffffffffu, b, 1);
    if (lane == 0 || bprev != b) {
        atomicAdd(&g_csum[b * 4 + 0], px);
        atomicAdd(&g_csum[b * 4 + 1], py);
        atomicAdd(&g_csum[b * 4 + 2], pz);
        atomicAdd(&g_csum[b * 4 + 3], pc);
    }
}

__global__ void k_center_fin() {
    int b = threadIdx.x;
    if (b < Bb) {
        float c = fmaxf(g_csum[b * 4 + 3], 1.f);
        g_center[b * 3 + 0] = g_csum[b * 4 + 0] / c;
        g_center[b * 3 + 1] = g_csum[b * 4 + 1] / c;
        g_center[b * 3 + 2] = g_csum[b * 4 + 2] / c;
        g_csum[b * 4 + 0] = 0.f;
        g_csum[b * 4 + 1] = 0.f;
        g_csum[b * 4 + 2] = 0.f;
        g_csum[b * 4 + 3] = 0.f;
    }
}

__global__ void k_deg(const int* __restrict__ eidx) {
    int e = blockIdx.x * blockDim.x + threadIdx.x;
    if (e < Ee) atomicAdd(&g_deg[eidx[e]], 1);
}

// ------------------- counting sort -------------------
__global__ void k_scan1() {
    __shared__ int s[256];
    int i = blockIdx.x * 256 + threadIdx.x;
    int v = g_deg[i];
    s[threadIdx.x] = v;
    __syncthreads();
    for (int off = 1; off < 256; off <<= 1) {
        int t = (threadIdx.x >= off) ? s[threadIdx.x - off] : 0;
        __syncthreads();
        s[threadIdx.x] += t;
        __syncthreads();
    }
    g_rowstart[i] = s[threadIdx.x] - v;
    if (threadIdx.x == 255) g_blksum[blockIdx.x] = s[255];
}
__global__ void k_scan2() {
    __shared__ int s[256];
    int i = threadIdx.x;
    int v = g_blksum[i];
    s[i] = v;
    __syncthreads();
    for (int off = 1; off < 256; off <<= 1) {
        int t = (i >= off) ? s[i - off] : 0;
        __syncthreads();
        s[i] += t;
        __syncthreads();
    }
    g_blksum[i] = s[i] - v;
}
__global__ void k_scan3() {
    int i = blockIdx.x * blockDim.x + threadIdx.x;
    if (i < Nn) {
        int v = g_rowstart[i] + g_blksum[i >> 8];
        g_rowstart[i] = v;
        g_rowcur[i] = v;
        g_invdeg[i] = 1.f / fmaxf((float)g_deg[i], 1.f);
        g_deg[i] = 0;
    }
}
__global__ void k_scatter(const int* __restrict__ eidx) {
    int e = blockIdx.x * blockDim.x + threadIdx.x;
    if (e >= Ee) return;
    int r = eidx[e], c = eidx[Ee + e];
    int p = atomicAdd(&g_rowcur[r], 1);
    float dx = g_posrel[c * 3 + 0] - g_posrel[r * 3 + 0];
    float dy = g_posrel[c * 3 + 1] - g_posrel[r * 3 + 1];
    float dz = g_posrel[c * 3 + 2] - g_posrel[r * 3 + 2];
    g_srow[p] = r;
    g_scol[p] = c;
    g_sdist[p] = sqrtf(dx * dx + dy * dy + dz * dz);
}

// ------------------- msum zeroing (fires PDL trigger immediately) -------------------
__global__ void k_zero_msum() {
    gdc_launch_dependents();
    int i = blockIdx.x * blockDim.x + threadIdx.x;
    ((float4*)g_msum)[i] = make_float4(0.f, 0.f, 0.f, 0.f);
}

// ------------------- combined weight prep (fragment-linear fp16) -------------------
__global__ void k_prep(const float* __restrict__ mw1, const float* __restrict__ mw2,
                       const float* __restrict__ uw, const float* __restrict__ lin_w) {
    int idx = blockIdx.x * blockDim.x + threadIdx.x;
    if (idx < 24576) {
        int l = idx / 8192, r = idx % 8192;
        int ks = r >> 10, ntile = (r >> 5) & 31, lane = r & 31;
        int n = ntile * 8 + (lane >> 2);
        int k0 = ks * 16 + (lane & 3) * 2;
        const float* W = mw1 + l * 257 * 128;
        float v[4];
        #pragma unroll
        for (int q = 0; q < 4; q++) {
            int k = k0 + (q >> 1) * 8 + (q & 1);
            v[q] = (n < 128) ? W[k * 128 + n] : W[(128 + k) * 128 + (n - 128)];
        }
        g_w1f[idx] = make_uint2(pack_h2(v[0], v[1]), pack_h2(v[2], v[3]));
    } else if (idx < 36864) {
        int i = idx - 24576;
        int l = i / 4096, r = i % 4096;
        int ks = r >> 9, ntile = (r >> 5) & 15, lane = r & 31;
        int n = ntile * 8 + (lane >> 2);
        int k0 = ks * 16 + (lane & 3) * 2;
        const float* W = mw2 + l * 16384;
        float v[4];
        #pragma unroll
        for (int q = 0; q < 4; q++) {
            int k = k0 + (q >> 1) * 8 + (q & 1);
            v[q] = W[k * 128 + n];
        }
        g_w2f[i] = make_uint2(pack_h2(v[0], v[1]), pack_h2(v[2], v[3]));
    } else if (idx < 61440) {
        int i = idx - 36864;
        int l = i / 8192, r = i % 8192;
        int ks = r >> 9, ntile = (r >> 5) & 15, lane = r & 31;
        int n = ntile * 8 + (lane >> 2);
        int k0 = ks * 16 + (lane & 3) * 2;
        const float* W = uw + l * 32768;
        float v[4];
        #pragma unroll
        for (int q = 0; q < 4; q++) {
            int k = k0 + (q >> 1) * 8 + (q & 1);
            v[q] = W[k * 128 + n];
        }
        g_uf[i] = make_uint2(pack_h2(v[0], v[1]), pack_h2(v[2], v[3]));
    } else {
        int i = idx - 61440;
        int ks = i >> 9, ntile = (i >> 5) & 15, lane = i & 31;
        int n = ntile * 8 + (lane >> 2);
        int k0 = ks * 16 + (lane & 3) * 2;
        float v[4];
        #pragma unroll
        for (int q = 0; q < 4; q++) {
            int k = k0 + (q >> 1) * 8 + (q & 1);
            v[q] = lin_w[k * 128 + n];
        }
        g_linf[i] = make_uint2(pack_h2(v[0], v[1]), pack_h2(v[2], v[3]));
    }
}

// ------------------- node-kernel smem layout -------------------
#define GOFF_BIAS 0
#define GOFF_AUX  512
#define GOFF_IDX  2048
#define GOFF_B1   4096
#define GOFF_AHI  4608
#define G_ASZ     34816
#define GOFF_ALO  (GOFF_AHI + G_ASZ)
#define G_SMEM    (GOFF_ALO + G_ASZ)   // 74240 -> occupancy 2

// ------------------- k_input_xab -------------------
__global__ void __launch_bounds__(512, 2)
k_input_xab(const float* __restrict__ pos, const int* __restrict__ z,
            const int* __restrict__ batch, const float* __restrict__ emb,
            const float* __restrict__ lin_w, const float* __restrict__ bias,
            const float* __restrict__ b1n) {
    extern __shared__ __align__(16) char sm[];
    uint32_t sbase = smem_u32(sm);
    int tid = threadIdx.x;
    int lane = tid & 31;
    int wid = tid >> 5;
    int wm = wid & 7, wn = wid >> 3;
    int n0 = blockIdx.x * 128;
    float* bs  = (float*)(sm + GOFF_BIAS);
    float* tl  = (float*)(sm + GOFF_AUX);
    float* prs = (float*)(sm + GOFF_IDX);
    int*   zs  = (int*)(sm + GOFF_IDX + 1536);
    float* b1s = (float*)(sm + GOFF_B1);

    if (tid < 128) {
        bs[tid] = bias[tid];
        b1s[tid] = b1n[tid];
        int n = n0 + tid;
        int b = batch[n];
        #pragma unroll
        for (int d = 0; d < 3; d++) {
            float v = pos[n * 3 + d] - g_center[b * 3 + d];
            prs[tid * 3 + d] = v;
            g_posrel[n * 3 + d] = v;
        }
        zs[tid] = z[n];
    } else if (tid >= 128 && tid < 128 + 384) {
        int i = tid - 128;
        tl[i] = lin_w[(128 + (i >> 7)) * 128 + (i & 127)];
    }
    __syncthreads();

    #pragma unroll
    for (int it = 0; it < 4; it++) {
        int cid = tid + it * 512;
        int r = cid >> 4, kc = cid & 15;
        const float4* ep = (const float4*)(emb + (size_t)zs[r] * 128) + kc * 2;
        float4 e0 = ep[0], e1 = ep[1];
        uint32_t h0, l0, h1, l1, h2, l2, h3, l3;
        split2(e0.x, e0.y, h0, l0);
        split2(e0.z, e0.w, h1, l1);
        split2(e1.x, e1.y, h2, l2);
        split2(e1.z, e1.w, h3, l3);
        uint32_t o = (uint32_t)r * 272 + kc * 16;
        *(uint4*)(sm + GOFF_AHI + o) = make_uint4(h0, h1, h2, h3);
        *(uint4*)(sm + GOFF_ALO + o) = make_uint4(l0, l1, l2, l3);
    }
    __syncthreads();

    float acc[8][4];
    ACC_ZERO(acc)
    mma2_gf(sbase, GOFF_AHI, GOFF_ALO, g_linf, 16, wn * 8, 0, lane, wm, acc);
    __syncthreads();
    stage_acc(sm, GOFF_AHI, lane, wm, wn, acc);
    __syncthreads();

    uint4 chi[4], clo[4];
    #pragma unroll
    for (int it = 0; it < 4; it++) {
        int cid = tid + it * 512;
        int r = cid >> 4, kc = cid & 15;
        float4 v0 = *(float4*)(sm + GOFF_AHI + (uint32_t)r * 528 + kc * 32);
        float4 v1 = *(float4*)(sm + GOFF_AHI + (uint32_t)r * 528 + kc * 32 + 16);
        float p0 = prs[r * 3 + 0], p1 = prs[r * 3 + 1], p2 = prs[r * 3 + 2];
        int c = kc * 8;
        v0.x += bs[c + 0] + p0 * tl[c + 0] + p1 * tl[128 + c + 0] + p2 * tl[256 + c + 0];
        v0.y += bs[c + 1] + p0 * tl[c + 1] + p1 * tl[128 + c + 1] + p2 * tl[256 + c + 1];
        v0.z += bs[c + 2] + p0 * tl[c + 2] + p1 * tl[128 + c + 2] + p2 * tl[256 + c + 2];
        v0.w += bs[c + 3] + p0 * tl[c + 3] + p1 * tl[128 + c + 3] + p2 * tl[256 + c + 3];
        v1.x += bs[c + 4] + p0 * tl[c + 4] + p1 * tl[128 + c + 4] + p2 * tl[256 + c + 4];
        v1.y += bs[c + 5] + p0 * tl[c + 5] + p1 * tl[128 + c + 5] + p2 * tl[256 + c + 5];
        v1.z += bs[c + 6] + p0 * tl[c + 6] + p1 * tl[128 + c + 6] + p2 * tl[256 + c + 6];
        v1.w += bs[c + 7] + p0 * tl[c + 7] + p1 * tl[128 + c + 7] + p2 * tl[256 + c + 7];
        uint32_t h0, l0, h1, l1, h2, l2, h3, l3;
        split2(v0.x, v0.y, h0, l0);
        split2(v0.z, v0.w, h1, l1);
        split2(v1.x, v1.y, h2, l2);
        split2(v1.z, v1.w, h3, l3);
        chi[it] = make_uint4(h0, h1, h2, h3);
        clo[it] = make_uint4(l0, l1, l2, l3);
        size_t nrow = (size_t)(n0 + r);
        ((uint4*)g_xhi)[nrow * 16 + kc] = chi[it];
        ((uint4*)g_xlo)[nrow * 16 + kc] = clo[it];
    }
    __syncthreads();
    #pragma unroll
    for (int it = 0; it < 4; it++) {
        int cid = tid + it * 512;
        int r = cid >> 4, kc = cid & 15;
        uint32_t o = (uint32_t)r * 272 + kc * 16;
        *(uint4*)(sm + GOFF_AHI + o) = chi[it];
        *(uint4*)(sm + GOFF_ALO + o) = clo[it];
    }
    __syncthreads();

    #pragma unroll
    for (int half = 0; half < 2; half++) {
        ACC_ZERO(acc)
        mma2_gf(sbase, GOFF_AHI, GOFF_ALO, g_w1f,
                32, half * 16 + wn * 8, 0, lane, wm, acc);
        write_frag_out(half == 0 ? g_xa : g_xb, n0, lane, wm, wn,
                       half == 0 ? b1s : (const float*)nullptr, acc);
    }
}

// ------------------- k_update_xab (PDL dependent: pass0 overlaps edge) ---------------
__global__ void __launch_bounds__(512, 2)
k_update_xab(const float* __restrict__ bias, int layer,
             const float* __restrict__ b1n, int do_next) {
    extern __shared__ __align__(16) char sm[];
    uint32_t sbase = smem_u32(sm);
    int tid = threadIdx.x;
    int lane = tid & 31;
    int wid = tid >> 5;
    int wm = wid & 7, wn = wid >> 3;
    int n0 = blockIdx.x * 128;
    float* bs = (float*)(sm + GOFF_BIAS);
    float* idg = (float*)(sm + GOFF_AUX);
    float* b1s = (float*)(sm + GOFF_B1);
    if (tid < 128) {
        bs[tid] = bias[tid];
        idg[tid] = g_invdeg[n0 + tid];
        b1s[tid] = do_next ? b1n[tid] : 0.f;
    }

    const uint2* uf = g_uf + layer * 8192;

    float acc[8][4];
    ACC_ZERO(acc)

    // pass 0: A = x hi/lo (no conflict with still-running edge kernel)
    {
        const uint4* ah = (const uint4*)g_xhi + (size_t)n0 * 16;
        const uint4* al = (const uint4*)g_xlo + (size_t)n0 * 16;
        #pragma unroll
        for (int it = 0; it < 4; it++) {
            int cid = tid + it * 512;
            int r = cid >> 4, c = cid & 15;
            uint32_t o = (uint32_t)r * 272 + c * 16;
            *(uint4*)(sm + GOFF_AHI + o) = ah[r * 16 + c];
            *(uint4*)(sm + GOFF_ALO + o) = al[r * 16 + c];
        }
        __syncthreads();
        mma2_gf(sbase, GOFF_AHI, GOFF_ALO, uf, 16, wn * 8, 0, lane, wm, acc);
        __syncthreads();
    }
    // pass 1: wait for edge grid completion, then consume msum
    gdc_wait();
    {
        #pragma unroll
        for (int it = 0; it < 4; it++) {
            int cid = tid + it * 512;
            int r = cid >> 4, c = cid & 15;
            uint32_t o = (uint32_t)r * 272 + c * 16;
            const float4* mp = (const float4*)(g_msum + (size_t)(n0 + r) * 128) + c * 2;
            float s = idg[r];
            float4 m0 = mp[0], m1 = mp[1];
            uint32_t h0, l0, h1, l1, h2, l2, h3, l3;
            split2(m0.x * s, m0.y * s, h0, l0);
            split2(m0.z * s, m0.w * s, h1, l1);
            split2(m1.x * s, m1.y * s, h2, l2);
            split2(m1.z * s, m1.w * s, h3, l3);
            *(uint4*)(sm + GOFF_AHI + o) = make_uint4(h0, h1, h2, h3);
            *(uint4*)(sm + GOFF_ALO + o) = make_uint4(l0, l1, l2, l3);
        }
        __syncthreads();
        mma2_gf(sbase, GOFF_AHI, GOFF_ALO, uf, 16, wn * 8, 8, lane, wm, acc);
        __syncthreads();
    }

    stage_acc(sm, GOFF_AHI, lane, wm, wn, acc);
    __syncthreads();

    uint4 chi[4], clo[4];
    #pragma unroll
    for (int it = 0; it < 4; it++) {
        int cid = tid + it * 512;
        int r = cid >> 4, kc = cid & 15;
        float4 v0 = *(float4*)(sm + GOFF_AHI + (uint32_t)r * 528 + kc * 32);
        float4 v1 = *(float4*)(sm + GOFF_AHI + (uint32_t)r * 528 + kc * 32 + 16);
        int c = kc * 8;
        v0.x = fmaxf(v0.x + bs[c + 0], 0.f);
        v0.y = fmaxf(v0.y + bs[c + 1], 0.f);
        v0.z = fmaxf(v0.z + bs[c + 2], 0.f);
        v0.w = fmaxf(v0.w + bs[c + 3], 0.f);
        v1.x = fmaxf(v1.x + bs[c + 4], 0.f);
        v1.y = fmaxf(v1.y + bs[c + 5], 0.f);
        v1.z = fmaxf(v1.z + bs[c + 6], 0.f);
        v1.w = fmaxf(v1.w + bs[c + 7], 0.f);
        size_t nrow = (size_t)(n0 + r);
        if (do_next) {
            uint32_t h0, l0, h1, l1, h2, l2, h3, l3;
            split2(v0.x, v0.y, h0, l0);
            split2(v0.z, v0.w, h1, l1);
            split2(v1.x, v1.y, h2, l2);
            split2(v1.z, v1.w, h3, l3);
            chi[it] = make_uint4(h0, h1, h2, h3);
            clo[it] = make_uint4(l0, l1, l2, l3);
            ((uint4*)g_xhi)[nrow * 16 + kc] = chi[it];
            ((uint4*)g_xlo)[nrow * 16 + kc] = clo[it];
        } else {
            ((float4*)(g_x0 + nrow * 128))[kc * 2] = v0;
            ((float4*)(g_x0 + nrow * 128))[kc * 2 + 1] = v1;
        }
    }
    if (!do_next) return;
    __syncthreads();
    #pragma unroll
    for (int it = 0; it < 4; it++) {
        int cid = tid + it * 512;
        int r = cid >> 4, kc = cid & 15;
        uint32_t o = (uint32_t)r * 272 + kc * 16;
        *(uint4*)(sm + GOFF_AHI + o) = chi[it];
        *(uint4*)(sm + GOFF_ALO + o) = clo[it];
    }
    __syncthreads();

    const uint2* w1 = g_w1f + (layer + 1) * 8192;
    #pragma unroll
    for (int half = 0; half < 2; half++) {
        ACC_ZERO(acc)
        mma2_gf(sbase, GOFF_AHI, GOFF_ALO, w1,
                32, half * 16 + wn * 8, 0, lane, wm, acc);
        write_frag_out(half == 0 ? g_xa : g_xb, n0, lane, wm, wn,
                       half == 0 ? b1s : (const float*)nullptr, acc);
    }
}

// ------------------- HMMA edge kernel (PDL) -------------------
#define EOFF_ROWS 0
#define EOFF_COLS 512
#define EOFF_DIST 1024
#define EOFF_BIAS 1536
#define EOFF_W1C  2048
#define EOFF_SEG  2560
#define EOFF_AHI  4096
#define E_ASZ     34816
#define EOFF_ALO  (EOFF_AHI + E_ASZ)
#define E_SMEM    (EOFF_ALO + E_ASZ)   // 73728 -> occupancy 2

__global__ void __launch_bounds__(512, 2)
k_edge_mma(const float* __restrict__ w1c, const float* __restrict__ b2, int layer) {
    gdc_launch_dependents();
    extern __shared__ __align__(16) char sm[];
    uint32_t sbase = smem_u32(sm);
    int tid = threadIdx.x;
    int lane = tid & 31;
    int wid = tid >> 5;
    int wm = wid & 7, wn = wid >> 3;
    int e0 = blockIdx.x * 128;

    int*   rows = (int*)(sm + EOFF_ROWS);
    int*   cols = (int*)(sm + EOFF_COLS);
    float* ds   = (float*)(sm + EOFF_DIST);
    float* bs   = (float*)(sm + EOFF_BIAS);
    float* ws   = (float*)(sm + EOFF_W1C);
    int*   wcnt = (int*)(sm + EOFF_SEG);
    int*   woff = wcnt + 4;
    int*   nsegp = woff + 4;
    int*   segstart = nsegp + 1;

    if (tid < 128) {
        rows[tid] = g_srow[e0 + tid];
        cols[tid] = g_scol[e0 + tid];
        ds[tid]   = g_sdist[e0 + tid];
        bs[tid]   = b2[tid];
        ws[tid]   = w1c[tid];
    }
    __syncthreads();

    #pragma unroll
    for (int it = 0; it < 4; it++) {
        int cid = tid + it * 512;
        int e = cid >> 4;
        int kc = cid & 15;
        const float4* pa = (const float4*)(g_xa + (size_t)cols[e] * 128) + kc * 2;
        const float4* pb = (const float4*)(g_xb + (size_t)rows[e] * 128) + kc * 2;
        float d = ds[e];
        float4 a0 = pa[0], a1 = pa[1];
        float4 b0 = pb[0], b1 = pb[1];
        int k0 = kc * 8;
        float v0 = fmaxf(a0.x + b0.x + d * ws[k0 + 0], 0.f);
        float v1 = fmaxf(a0.y + b0.y + d * ws[k0 + 1], 0.f);
        float v2 = fmaxf(a0.z + b0.z + d * ws[k0 + 2], 0.f);
        float v3 = fmaxf(a0.w + b0.w + d * ws[k0 + 3], 0.f);
        float v4 = fmaxf(a1.x + b1.x + d * ws[k0 + 4], 0.f);
        float v5 = fmaxf(a1.y + b1.y + d * ws[k0 + 5], 0.f);
        float v6 = fmaxf(a1.z + b1.z + d * ws[k0 + 6], 0.f);
        float v7 = fmaxf(a1.w + b1.w + d * ws[k0 + 7], 0.f);
        uint32_t h0, l0, h1, l1, h2, l2, h3, l3;
        split2(v0, v1, h0, l0);
        split2(v2, v3, h1, l1);
        split2(v4, v5, h2, l2);
        split2(v6, v7, h3, l3);
        uint32_t o = (uint32_t)e * 272 + kc * 16;
        *(uint4*)(sm + EOFF_AHI + o) = make_uint4(h0, h1, h2, h3);
        *(uint4*)(sm + EOFF_ALO + o) = make_uint4(l0, l1, l2, l3);
    }
    __syncthreads();

    float acc[8][4];
    ACC_ZERO(acc)
    mma2_gf(sbase, EOFF_AHI, EOFF_ALO, g_w2f + layer * 4096,
            16, wn * 8, 0, lane, wm, acc);
    __syncthreads();
    stage_acc(sm, EOFF_AHI, lane, wm, wn, acc);

    int f = 0, pre = 0;
    if (wid < 4) {
        f = (tid == 0) || (rows[tid] != rows[tid - 1]);
        unsigned m = __ballot_sync(0xffffffffu, f);
        pre = __popc(m & ((1u << lane) - 1u));
        if (lane == 0) wcnt[wid] = __popc(m);
    }
    __syncthreads();
    if (tid == 0) {
        int s = 0;
        #pragma unroll
        for (int w = 0; w < 4; w++) { woff[w] = s; s += wcnt[w]; }
        nsegp[0] = s;
        segstart[s] = 128;
    }
    __syncthreads();
    if (wid < 4 && f) segstart[woff[wid] + pre] = tid;
    __syncthreads();

    gdc_wait();
    int nseg = nsegp[0];
    for (int item = tid; item < nseg * 32; item += 512) {
        int s = item >> 5, c4 = item & 31;
        int rbeg = segstart[s], rend = segstart[s + 1];
        float4 bb = *(float4*)(bs + c4 * 4);
        float m0 = 0.f, m1 = 0.f, m2 = 0.f, m3 = 0.f;
        for (int r = rbeg; r < rend; r++) {
            float4 v = *(float4*)(sm + EOFF_AHI + (uint32_t)r * 528 + c4 * 16);
            m0 += fmaxf(v.x + bb.x, 0.f);
            m1 += fmaxf(v.y + bb.y, 0.f);
            m2 += fmaxf(v.z + bb.z, 0.f);
            m3 += fmaxf(v.w + bb.w, 0.f);
        }
        float* p = g_msum + (size_t)rows[rbeg] * 128 + c4 * 4;
        asm volatile("red.global.add.v4.f32 [%0], {%1,%2,%3,%4};"
                     :: "l"(p), "f"(m0), "f"(m1), "f"(m2), "f"(m3) : "memory");
    }
}

// ------------------- readout pooling (fused ligcnt) -------------------
__global__ void k_pool(const int* __restrict__ batch, const int* __restrict__ ntype) {
    int idx = blockIdx.x * blockDim.x + threadIdx.x;
    int n = idx >> 5;
    int q = idx & 31;
    if (n >= Nn) return;
    if (ntype[n] == 1) {
        int b = batch[n];
        float4 v = ((const float4*)g_x0)[n * 32 + q];
        float* p = &g_gsum[b * 128 + q * 4];
        asm volatile("red.global.add.v4.f32 [%0], {%1,%2,%3,%4};"
                     :: "l"(p), "f"(v.x), "f"(v.y), "f"(v.z), "f"(v.w) : "memory");
        if (q == 0) atomicAdd(&g_ligcnt[b], 1.f);
    }
}

__global__ void __launch_bounds__(128)
k_readout(const float* __restrict__ rw1, const float* __restrict__ rb1,
          const float* __restrict__ rw2, const float* __restrict__ rb2,
          float* __restrict__ out) {
    __shared__ __align__(16) float gs[128];
    __shared__ float red_s[128];
    int b = blockIdx.x;
    int tid = threadIdx.x;
    float cnt = fmaxf(g_ligcnt[b], 1.f);
    gs[tid] = g_gsum[b * 128 + tid] / cnt;
    g_gsum[b * 128 + tid] = 0.f;
    if (tid == 0) g_ligcnt[b] = 0.f;
    __syncthreads();

    int j = tid;
    const float* Wj = rw1 + j;
    const float4* gs4 = (const float4*)gs;
    float acc = rb1[j];
    for (int kk = 0; kk < 32; kk++) {
        float w0 = Wj[(kk * 4 + 0) * 128];
        float w1 = Wj[(kk * 4 + 1) * 128];
        float w2 = Wj[(kk * 4 + 2) * 128];
        float w3 = Wj[(kk * 4 + 3) * 128];
        float4 gv = gs4[kk];
        acc += gv.x * w0 + gv.y * w1 + gv.z * w2 + gv.w * w3;
    }
    float hg = fmaxf(acc, 0.f);
    red_s[tid] = hg * rw2[j];
    __syncthreads();
    for (int s = 64; s > 0; s >>= 1) {
        if (tid < s) red_s[tid] += red_s[tid + s];
        __syncthreads();
    }
    if (tid == 0) out[b] = red_s[0] + rb2[0];
}

// ------------------- launch -------------------
extern "C" void kernel_launch(void* const* d_in, const int* in_sizes, int n_in,
                              void* d_out, int out_size) {
    const float* pos   = (const float*)d_in[0];
    const int*   z     = (const int*)d_in[1];
    const int*   batch = (const int*)d_in[2];
    const int*   eidx  = (const int*)d_in[3];
    const int*   ntype = (const int*)d_in[4];
    const float* emb   = (const float*)d_in[5];
    const float* lin_w = (const float*)d_in[6];
    const float* lin_b = (const float*)d_in[7];
    const float* mw1   = (const float*)d_in[8];
    const float* mb1   = (const float*)d_in[9];
    const float* mw2   = (const float*)d_in[10];
    const float* mb2   = (const float*)d_in[11];
    const float* uw    = (const float*)d_in[12];
    const float* ub    = (const float*)d_in[13];
    const float* rw1   = (const float*)d_in[14];
    const float* rb1   = (const float*)d_in[15];
    const float* rw2   = (const float*)d_in[16];
    const float* rb2   = (const float*)d_in[17];
    float* out = (float*)d_out;

    cudaFuncSetAttribute(k_edge_mma, cudaFuncAttributeMaxDynamicSharedMemorySize, E_SMEM);
    cudaFuncSetAttribute(k_input_xab, cudaFuncAttributeMaxDynamicSharedMemorySize, G_SMEM);
    cudaFuncSetAttribute(k_update_xab, cudaFuncAttributeMaxDynamicSharedMemorySize, G_SMEM);

    k_prep<<<256, 256>>>(mw1, mw2, uw, lin_w);
    k_center_sum<<<Nn / 256, 256>>>(pos, batch);
    k_center_fin<<<1, 64>>>();
    k_input_xab<<<Nn / 128, 512, G_SMEM>>>(pos, z, batch, emb, lin_w, lin_b, mb1);
    k_deg<<<Ee / 256, 256>>>(eidx);
    k_scan1<<<256, 256>>>();
    k_scan2<<<1, 256>>>();
    k_scan3<<<Nn / 256, 256>>>();
    k_scatter<<<Ee / 256, 256>>>(eidx);

    cudaLaunchAttribute pdl[1];
    pdl[0].id = cudaLaunchAttributeProgrammaticStreamSerialization;
    pdl[0].val.programmaticStreamSerializationAllowed = 1;

    for (int l = 0; l < 3; l++) {
        const float* W1 = mw1 + l * 257 * 128;
        k_zero_msum<<<(Nn * Hh / 4) / 512, 512>>>();

        cudaLaunchConfig_t ecfg = {};
        ecfg.gridDim = dim3(Ee / 128);
        ecfg.blockDim = dim3(512);
        ecfg.dynamicSmemBytes = E_SMEM;
        ecfg.attrs = pdl;
        ecfg.numAttrs = 1;
        cudaLaunchKernelEx(&ecfg, k_edge_mma, W1 + 256 * 128, mb2 + l * 128, l);

        cudaLaunchConfig_t ucfg = {};
        ucfg.gridDim = dim3(Nn / 128);
        ucfg.blockDim = dim3(512);
        ucfg.dynamicSmemBytes = G_SMEM;
        ucfg.attrs = pdl;
        ucfg.numAttrs = 1;
        cudaLaunchKernelEx(&ucfg, k_update_xab, ub + l * 128, l,
                           l < 2 ? (mb1 + (l + 1) * 128) : mb1, l < 2 ? 1 : 0);
    }

    k_pool<<<Nn * 32 / 256, 256>>>(batch, ntype);
    k_readout<<<Bb, 128>>>(rw1, rb1, rw2, rb2, out);
}

// round 15
// speedup vs baseline: 1.0149x; 1.0149x over previous
#include <cuda_runtime.h>
#include <cuda_fp16.h>
#include <math.h>
#include <stdint.h>

#define Nn 65536
#define Ee 1048576
#define Bb 64
#define Hh 128

// ------------------- scratch (static device globals) -------------------
__device__ float g_csum[Bb * 4];
__device__ float g_center[Bb * 3];
__device__ float g_posrel[Nn * 3];
__device__ float g_x0[Nn * Hh];
__device__ uint32_t g_xhi[Nn * 64];       // fp16x2-packed hi split of x
__device__ uint32_t g_xlo[Nn * 64];       // fp16x2-packed lo split (residual)
__device__ float g_xa[Nn * Hh];
__device__ float g_xb[Nn * Hh];
__device__ float g_msum[Nn * Hh];
__device__ int   g_deg[Nn];
__device__ float g_invdeg[Nn];
__device__ float g_gsum[Bb * Hh];
__device__ float g_ligcnt[Bb];
// edge sort scratch
__device__ int   g_rowstart[Nn];
__device__ int   g_rowcur[Nn];
__device__ int   g_blksum[256];
__device__ int   g_srow[Ee];
__device__ int   g_scol[Ee];
__device__ float g_sdist[Ee];
// fragment-linear weights (fp16x2 pairs per lane)
__device__ uint2 g_w1f[3 * 8192];   // W1^T 256n x 128k, NT=32
__device__ uint2 g_w2f[3 * 4096];   // W2^T 128n x 128k, NT=16
__device__ uint2 g_uf[3 * 8192];    // U^T  128n x 256k, NT=16
__device__ uint2 g_linf[4096];      // lin^T 128n x 128k, NT=16

// ------------------- helpers -------------------
__device__ __forceinline__ uint32_t smem_u32(const void* p) {
    uint32_t a;
    asm("{ .reg .u64 t; cvta.to.shared.u64 t, %1; cvt.u32.u64 %0, t; }" : "=r"(a) : "l"(p));
    return a;
}
__device__ __forceinline__ void ldsm_x4(uint32_t* r, uint32_t addr) {
    asm volatile("ldmatrix.sync.aligned.m8n8.x4.shared.b16 {%0,%1,%2,%3}, [%4];"
                 : "=r"(r[0]), "=r"(r[1]), "=r"(r[2]), "=r"(r[3]) : "r"(addr));
}
__device__ __forceinline__ void mma_f16(float* d, const uint32_t* a, const uint32_t* b) {
    asm volatile("mma.sync.aligned.m16n8k16.row.col.f32.f16.f16.f32 "
                 "{%0,%1,%2,%3}, {%4,%5,%6,%7}, {%8,%9}, {%0,%1,%2,%3};"
                 : "+f"(d[0]), "+f"(d[1]), "+f"(d[2]), "+f"(d[3])
                 : "r"(a[0]), "r"(a[1]), "r"(a[2]), "r"(a[3]), "r"(b[0]), "r"(b[1]));
}
__device__ __forceinline__ void split2(float v0, float v1, uint32_t& hi, uint32_t& lo) {
    __half2 h = __floats2half2_rn(v0, v1);
    float h0 = __half2float(__low2half(h));
    float h1 = __half2float(__high2half(h));
    __half2 l = __floats2half2_rn(v0 - h0, v1 - h1);
    hi = *(uint32_t*)&h;
    lo = *(uint32_t*)&l;
}
__device__ __forceinline__ uint32_t pack_h2(float v0, float v1) {
    __half2 h = __floats2half2_rn(v0, v1);
    return *(uint32_t*)&h;
}
// PDL primitives (sm_90+ PTX, no arch suffix)
__device__ __forceinline__ void gdc_launch_dependents() {
    asm volatile("griddepcontrol.launch_dependents;");
}
__device__ __forceinline__ void gdc_wait() {
    asm volatile("griddepcontrol.wait;" ::: "memory");
}

// 2-term MMA core: D += (Ahi + Alo) * Bhi. B from fragment-linear global arrays.
// warp tile m32 x n32 (4 warp_m x 4 warp_n) — R13 configuration.
__device__ __forceinline__ void mma2_gf(uint32_t sbase, uint32_t oAhi, uint32_t oAlo,
                                        const uint2* __restrict__ bf,
                                        int NT, int nt_base, int ks_base,
                                        int lane, int warp_m,
                                        float (&acc)[2][4][4]) {
    uint32_t a_base = sbase + oAhi + (uint32_t)(warp_m * 32 + (lane & 15)) * 272 + (uint32_t)(lane >> 4) * 16;
    uint32_t dA = oAlo - oAhi;
    for (int ks = 0; ks < 8; ks++) {
        uint32_t kb = (uint32_t)ks * 32;
        uint32_t a_hi[2][4], a_lo[2][4];
        #pragma unroll
        for (int mt = 0; mt < 2; mt++) {
            uint32_t ad = a_base + (uint32_t)(mt * 16) * 272 + kb;
            ldsm_x4(a_hi[mt], ad);
            ldsm_x4(a_lo[mt], ad + dA);
        }
        int fks = (ks_base + ks) * NT + nt_base;
        #pragma unroll
        for (int nt = 0; nt < 4; nt++) {
            uint2 bh = __ldg(bf + (size_t)(fks + nt) * 32 + lane);
            uint32_t bhv[2] = {bh.x, bh.y};
            mma_f16(acc[0][nt], a_hi[0], bhv);
            mma_f16(acc[1][nt], a_hi[1], bhv);
            mma_f16(acc[0][nt], a_lo[0], bhv);
            mma_f16(acc[1][nt], a_lo[1], bhv);
        }
    }
}

__device__ __forceinline__ void stage_acc(char* sm, uint32_t oM, int lane, int warp_m, int warp_n,
                                          float (&acc)[2][4][4]) {
    #pragma unroll
    for (int mt = 0; mt < 2; mt++) {
        int er = warp_m * 32 + mt * 16 + (lane >> 2);
        #pragma unroll
        for (int nt = 0; nt < 4; nt++) {
            int cb = warp_n * 32 + nt * 8 + (lane & 3) * 2;
            *(float2*)(sm + oM + (uint32_t)er * 528 + cb * 4) = make_float2(acc[mt][nt][0], acc[mt][nt][1]);
            *(float2*)(sm + oM + (uint32_t)(er + 8) * 528 + cb * 4) = make_float2(acc[mt][nt][2], acc[mt][nt][3]);
        }
    }
}

__device__ __forceinline__ void write_frag_out(float* out, int n0, int lane, int warp_m, int warp_n,
                                               const float* bsm, float (&acc)[2][4][4]) {
    #pragma unroll
    for (int mt = 0; mt < 2; mt++) {
        int er = n0 + warp_m * 32 + mt * 16 + (lane >> 2);
        #pragma unroll
        for (int nt = 0; nt < 4; nt++) {
            int cb = warp_n * 32 + nt * 8 + (lane & 3) * 2;
            float b0 = bsm ? bsm[cb] : 0.f;
            float b1 = bsm ? bsm[cb + 1] : 0.f;
            *(float2*)(out + (size_t)er * 128 + cb) = make_float2(acc[mt][nt][0] + b0, acc[mt][nt][1] + b1);
            *(float2*)(out + (size_t)(er + 8) * 128 + cb) = make_float2(acc[mt][nt][2] + b0, acc[mt][nt][3] + b1);
        }
    }
}

#define ACC_ZERO(acc) \
    _Pragma("unroll") \
    for (int mt = 0; mt < 2; mt++) \
        _Pragma("unroll") \
        for (int nt = 0; nt < 4; nt++) \
            _Pragma("unroll") \
            for (int q = 0; q < 4; q++) (acc)[mt][nt][q] = 0.f;

// ------------------- small kernels -------------------
__global__ void k_center_sum(const float* __restrict__ pos, const int* __restrict__ batch) {
    int n = blockIdx.x * blockDim.x + threadIdx.x;
    if (n >= Nn) return;
    int lane = threadIdx.x & 31;
    int b = batch[n];
    float px = pos[n * 3 + 0], py = pos[n * 3 + 1], pz = pos[n * 3 + 2], pc = 1.f;
    #pragma unroll
    for (int off = 1; off < 32; off <<= 1) {
        int bs = __shfl_down_sync(0xffffffffu, b, off);
        float tx = __shfl_down_sync(0xffffffffu, px, off);
        float ty = __shfl_down_sync(0xffffffffu, py, off);
        float tz = __shfl_down_sync(0xffffffffu, pz, off);
        float tc = __shfl_down_sync(0xffffffffu, pc, off);
        if (lane + off < 32 && bs == b) { px += tx; py += ty; pz += tz; pc += tc; }
    }
    int bprev = __shfl_up_sync(0xffffffffu, b, 1);
    if (lane == 0 || bprev != b) {
        atomicAdd(&g_csum[b * 4 + 0], px);
        atomicAdd(&g_csum[b * 4 + 1], py);
        atomicAdd(&g_csum[b * 4 + 2], pz);
        atomicAdd(&g_csum[b * 4 + 3], pc);
    }
}

__global__ void k_center_fin() {
    int b = threadIdx.x;
    if (b < Bb) {
        float c = fmaxf(g_csum[b * 4 + 3], 1.f);
        g_center[b * 3 + 0] = g_csum[b * 4 + 0] / c;
        g_center[b * 3 + 1] = g_csum[b * 4 + 1] / c;
        g_center[b * 3 + 2] = g_csum[b * 4 + 2] / c;
        g_csum[b * 4 + 0] = 0.f;
        g_csum[b * 4 + 1] = 0.f;
        g_csum[b * 4 + 2] = 0.f;
        g_csum[b * 4 + 3] = 0.f;
    }
}

// k_deg is a PDL consumer: only touches eidx/g_deg, safe to overlap k_input_xab
__global__ void k_deg(const int* __restrict__ eidx) {
    int e = blockIdx.x * blockDim.x + threadIdx.x;
    if (e < Ee) atomicAdd(&g_deg[eidx[e]], 1);
}

// ------------------- counting sort -------------------
__global__ void k_scan1() {
    __shared__ int s[256];
    int i = blockIdx.x * 256 + threadIdx.x;
    int v = g_deg[i];
    s[threadIdx.x] = v;
    __syncthreads();
    for (int off = 1; off < 256; off <<= 1) {
        int t = (threadIdx.x >= off) ? s[threadIdx.x - off] : 0;
        __syncthreads();
        s[threadIdx.x] += t;
        __syncthreads();
    }
    g_rowstart[i] = s[threadIdx.x] - v;
    if (threadIdx.x == 255) g_blksum[blockIdx.x] = s[255];
}
__global__ void k_scan2() {
    __shared__ int s[256];
    int i = threadIdx.x;
    int v = g_blksum[i];
    s[i] = v;
    __syncthreads();
    for (int off = 1; off < 256; off <<= 1) {
        int t = (i >= off) ? s[i - off] : 0;
        __syncthreads();
        s[i] += t;
        __syncthreads();
    }
    g_blksum[i] = s[i] - v;
}
__global__ void k_scan3() {
    int i = blockIdx.x * blockDim.x + threadIdx.x;
    if (i < Nn) {
        int v = g_rowstart[i] + g_blksum[i >> 8];
        g_rowstart[i] = v;
        g_rowcur[i] = v;
        g_invdeg[i] = 1.f / fmaxf((float)g_deg[i], 1.f);
        g_deg[i] = 0;
    }
}
__global__ void k_scatter(const int* __restrict__ eidx) {
    int e = blockIdx.x * blockDim.x + threadIdx.x;
    if (e >= Ee) return;
    int r = eidx[e], c = eidx[Ee + e];
    int p = atomicAdd(&g_rowcur[r], 1);
    float dx = g_posrel[c * 3 + 0] - g_posrel[r * 3 + 0];
    float dy = g_posrel[c * 3 + 1] - g_posrel[r * 3 + 1];
    float dz = g_posrel[c * 3 + 2] - g_posrel[r * 3 + 2];
    g_srow[p] = r;
    g_scol[p] = c;
    g_sdist[p] = sqrtf(dx * dx + dy * dy + dz * dz);
}

// ------------------- msum zeroing (PDL: waits for update's pass-1 reads, fires edge) --
__global__ void k_zero_msum() {
    gdc_wait();                 // ensure previous update finished reading msum
    gdc_launch_dependents();    // edge may dispatch behind us
    int i = blockIdx.x * blockDim.x + threadIdx.x;
    ((float4*)g_msum)[i] = make_float4(0.f, 0.f, 0.f, 0.f);
}

// ------------------- combined weight prep (fragment-linear fp16) -------------------
__global__ void k_prep(const float* __restrict__ mw1, const float* __restrict__ mw2,
                       const float* __restrict__ uw, const float* __restrict__ lin_w) {
    int idx = blockIdx.x * blockDim.x + threadIdx.x;
    if (idx < 24576) {
        int l = idx / 8192, r = idx % 8192;
        int ks = r >> 10, ntile = (r >> 5) & 31, lane = r & 31;
        int n = ntile * 8 + (lane >> 2);
        int k0 = ks * 16 + (lane & 3) * 2;
        const float* W = mw1 + l * 257 * 128;
        float v[4];
        #pragma unroll
        for (int q = 0; q < 4; q++) {
            int k = k0 + (q >> 1) * 8 + (q & 1);
            v[q] = (n < 128) ? W[k * 128 + n] : W[(128 + k) * 128 + (n - 128)];
        }
        g_w1f[idx] = make_uint2(pack_h2(v[0], v[1]), pack_h2(v[2], v[3]));
    } else if (idx < 36864) {
        int i = idx - 24576;
        int l = i / 4096, r = i % 4096;
        int ks = r >> 9, ntile = (r >> 5) & 15, lane = r & 31;
        int n = ntile * 8 + (lane >> 2);
        int k0 = ks * 16 + (lane & 3) * 2;
        const float* W = mw2 + l * 16384;
        float v[4];
        #pragma unroll
        for (int q = 0; q < 4; q++) {
            int k = k0 + (q >> 1) * 8 + (q & 1);
            v[q] = W[k * 128 + n];
        }
        g_w2f[i] = make_uint2(pack_h2(v[0], v[1]), pack_h2(v[2], v[3]));
    } else if (idx < 61440) {
        int i = idx - 36864;
        int l = i / 8192, r = i % 8192;
        int ks = r >> 9, ntile = (r >> 5) & 15, lane = r & 31;
        int n = ntile * 8 + (lane >> 2);
        int k0 = ks * 16 + (lane & 3) * 2;
        const float* W = uw + l * 32768;
        float v[4];
        #pragma unroll
        for (int q = 0; q < 4; q++) {
            int k = k0 + (q >> 1) * 8 + (q & 1);
            v[q] = W[k * 128 + n];
        }
        g_uf[i] = make_uint2(pack_h2(v[0], v[1]), pack_h2(v[2], v[3]));
    } else {
        int i = idx - 61440;
        int ks = i >> 9, ntile = (i >> 5) & 15, lane = i & 31;
        int n = ntile * 8 + (lane >> 2);
        int k0 = ks * 16 + (lane & 3) * 2;
        float v[4];
        #pragma unroll
        for (int q = 0; q < 4; q++) {
            int k = k0 + (q >> 1) * 8 + (q & 1);
            v[q] = lin_w[k * 128 + n];
        }
        g_linf[i] = make_uint2(pack_h2(v[0], v[1]), pack_h2(v[2], v[3]));
    }
}

// ------------------- node-kernel smem layout -------------------
#define GOFF_BIAS 0
#define GOFF_AUX  512
#define GOFF_IDX  2048
#define GOFF_B1   4096
#define GOFF_AHI  4608
#define G_ASZ     34816
#define GOFF_ALO  (GOFF_AHI + G_ASZ)
#define G_SMEM    (GOFF_ALO + G_ASZ)   // 74240 -> occupancy 2

// ------------------- k_input_xab (fires PDL for k_deg at entry) -------------------
__global__ void __launch_bounds__(512, 2)
k_input_xab(const float* __restrict__ pos, const int* __restrict__ z,
            const int* __restrict__ batch, const float* __restrict__ emb,
            const float* __restrict__ lin_w, const float* __restrict__ bias,
            const float* __restrict__ b1n) {
    gdc_launch_dependents();   // k_deg is independent; let it overlap us
    extern __shared__ __align__(16) char sm[];
    uint32_t sbase = smem_u32(sm);
    int tid = threadIdx.x;
    int lane = tid & 31;
    int wid = tid >> 5;
    int n0 = blockIdx.x * 128;
    float* bs  = (float*)(sm + GOFF_BIAS);
    float* tl  = (float*)(sm + GOFF_AUX);
    float* prs = (float*)(sm + GOFF_IDX);
    int*   zs  = (int*)(sm + GOFF_IDX + 1536);
    float* b1s = (float*)(sm + GOFF_B1);

    if (tid < 128) {
        bs[tid] = bias[tid];
        b1s[tid] = b1n[tid];
        int n = n0 + tid;
        int b = batch[n];
        #pragma unroll
        for (int d = 0; d < 3; d++) {
            float v = pos[n * 3 + d] - g_center[b * 3 + d];
            prs[tid * 3 + d] = v;
            g_posrel[n * 3 + d] = v;
        }
        zs[tid] = z[n];
    } else if (tid >= 128 && tid < 128 + 384) {
        int i = tid - 128;
        tl[i] = lin_w[(128 + (i >> 7)) * 128 + (i & 127)];
    }
    __syncthreads();

    #pragma unroll
    for (int it = 0; it < 4; it++) {
        int cid = tid + it * 512;
        int r = cid >> 4, kc = cid & 15;
        const float4* ep = (const float4*)(emb + (size_t)zs[r] * 128) + kc * 2;
        float4 e0 = ep[0], e1 = ep[1];
        uint32_t h0, l0, h1, l1, h2, l2, h3, l3;
        split2(e0.x, e0.y, h0, l0);
        split2(e0.z, e0.w, h1, l1);
        split2(e1.x, e1.y, h2, l2);
        split2(e1.z, e1.w, h3, l3);
        uint32_t o = (uint32_t)r * 272 + kc * 16;
        *(uint4*)(sm + GOFF_AHI + o) = make_uint4(h0, h1, h2, h3);
        *(uint4*)(sm + GOFF_ALO + o) = make_uint4(l0, l1, l2, l3);
    }
    __syncthreads();

    float acc[2][4][4];
    ACC_ZERO(acc)
    mma2_gf(sbase, GOFF_AHI, GOFF_ALO, g_linf, 16, (wid >> 2) * 4, 0, lane, wid & 3, acc);
    __syncthreads();
    stage_acc(sm, GOFF_AHI, lane, wid & 3, wid >> 2, acc);
    __syncthreads();

    uint4 chi[4], clo[4];
    #pragma unroll
    for (int it = 0; it < 4; it++) {
        int cid = tid + it * 512;
        int r = cid >> 4, kc = cid & 15;
        float4 v0 = *(float4*)(sm + GOFF_AHI + (uint32_t)r * 528 + kc * 32);
        float4 v1 = *(float4*)(sm + GOFF_AHI + (uint32_t)r * 528 + kc * 32 + 16);
        float p0 = prs[r * 3 + 0], p1 = prs[r * 3 + 1], p2 = prs[r * 3 + 2];
        int c = kc * 8;
        v0.x += bs[c + 0] + p0 * tl[c + 0] + p1 * tl[128 + c + 0] + p2 * tl[256 + c + 0];
        v0.y += bs[c + 1] + p0 * tl[c + 1] + p1 * tl[128 + c + 1] + p2 * tl[256 + c + 1];
        v0.z += bs[c + 2] + p0 * tl[c + 2] + p1 * tl[128 + c + 2] + p2 * tl[256 + c + 2];
        v0.w += bs[c + 3] + p0 * tl[c + 3] + p1 * tl[128 + c + 3] + p2 * tl[256 + c + 3];
        v1.x += bs[c + 4] + p0 * tl[c + 4] + p1 * tl[128 + c + 4] + p2 * tl[256 + c + 4];
        v1.y += bs[c + 5] + p0 * tl[c + 5] + p1 * tl[128 + c + 5] + p2 * tl[256 + c + 5];
        v1.z += bs[c + 6] + p0 * tl[c + 6] + p1 * tl[128 + c + 6] + p2 * tl[256 + c + 6];
        v1.w += bs[c + 7] + p0 * tl[c + 7] + p1 * tl[128 + c + 7] + p2 * tl[256 + c + 7];
        uint32_t h0, l0, h1, l1, h2, l2, h3, l3;
        split2(v0.x, v0.y, h0, l0);
        split2(v0.z, v0.w, h1, l1);
        split2(v1.x, v1.y, h2, l2);
        split2(v1.z, v1.w, h3, l3);
        chi[it] = make_uint4(h0, h1, h2, h3);
        clo[it] = make_uint4(l0, l1, l2, l3);
        size_t nrow = (size_t)(n0 + r);
        ((uint4*)g_xhi)[nrow * 16 + kc] = chi[it];
        ((uint4*)g_xlo)[nrow * 16 + kc] = clo[it];
    }
    __syncthreads();
    #pragma unroll
    for (int it = 0; it < 4; it++) {
        int cid = tid + it * 512;
        int r = cid >> 4, kc = cid & 15;
        uint32_t o = (uint32_t)r * 272 + kc * 16;
        *(uint4*)(sm + GOFF_AHI + o) = chi[it];
        *(uint4*)(sm + GOFF_ALO + o) = clo[it];
    }
    __syncthreads();

    #pragma unroll
    for (int half = 0; half < 2; half++) {
        ACC_ZERO(acc)
        mma2_gf(sbase, GOFF_AHI, GOFF_ALO, g_w1f,
                32, half * 16 + (wid >> 2) * 4, 0, lane, wid & 3, acc);
        write_frag_out(half == 0 ? g_xa : g_xb, n0, lane, wid & 3, wid >> 2,
                       half == 0 ? b1s : (const float*)nullptr, acc);
    }
}

// ------------------- k_update_xab (PDL: pass0 overlaps edge; fires zero after pass1) --
__global__ void __launch_bounds__(512, 2)
k_update_xab(const float* __restrict__ bias, int layer,
             const float* __restrict__ b1n, int do_next) {
    extern __shared__ __align__(16) char sm[];
    uint32_t sbase = smem_u32(sm);
    int tid = threadIdx.x;
    int lane = tid & 31;
    int wid = tid >> 5;
    int n0 = blockIdx.x * 128;
    float* bs = (float*)(sm + GOFF_BIAS);
    float* idg = (float*)(sm + GOFF_AUX);
    float* b1s = (float*)(sm + GOFF_B1);
    if (tid < 128) {
        bs[tid] = bias[tid];
        idg[tid] = g_invdeg[n0 + tid];
        b1s[tid] = do_next ? b1n[tid] : 0.f;
    }

    const uint2* uf = g_uf + layer * 8192;

    float acc[2][4][4];
    ACC_ZERO(acc)

    // pass 0: A = x hi/lo (no conflict with still-running edge kernel)
    {
        const uint4* ah = (const uint4*)g_xhi + (size_t)n0 * 16;
        const uint4* al = (const uint4*)g_xlo + (size_t)n0 * 16;
        #pragma unroll
        for (int it = 0; it < 4; it++) {
            int cid = tid + it * 512;
            int r = cid >> 4, c = cid & 15;
            uint32_t o = (uint32_t)r * 272 + c * 16;
            *(uint4*)(sm + GOFF_AHI + o) = ah[r * 16 + c];
            *(uint4*)(sm + GOFF_ALO + o) = al[r * 16 + c];
        }
        __syncthreads();
        mma2_gf(sbase, GOFF_AHI, GOFF_ALO, uf, 16, (wid >> 2) * 4, 0, lane, wid & 3, acc);
        __syncthreads();
    }
    // pass 1: wait for edge grid completion, consume msum, then release next zeroing
    gdc_wait();
    {
        #pragma unroll
        for (int it = 0; it < 4; it++) {
            int cid = tid + it * 512;
            int r = cid >> 4, c = cid & 15;
            uint32_t o = (uint32_t)r * 272 + c * 16;
            const float4* mp = (const float4*)(g_msum + (size_t)(n0 + r) * 128) + c * 2;
            float s = idg[r];
            float4 m0 = mp[0], m1 = mp[1];
            uint32_t h0, l0, h1, l1, h2, l2, h3, l3;
            split2(m0.x * s, m0.y * s, h0, l0);
            split2(m0.z * s, m0.w * s, h1, l1);
            split2(m1.x * s, m1.y * s, h2, l2);
            split2(m1.z * s, m1.w * s, h3, l3);
            *(uint4*)(sm + GOFF_AHI + o) = make_uint4(h0, h1, h2, h3);
            *(uint4*)(sm + GOFF_ALO + o) = make_uint4(l0, l1, l2, l3);
        }
        __syncthreads();
        gdc_launch_dependents();   // msum fully read: next k_zero_msum may start
        mma2_gf(sbase, GOFF_AHI, GOFF_ALO, uf, 16, (wid >> 2) * 4, 8, lane, wid & 3, acc);
        __syncthreads();
    }

    stage_acc(sm, GOFF_AHI, lane, wid & 3, wid >> 2, acc);
    __syncthreads();

    uint4 chi[4], clo[4];
    #pragma unroll
    for (int it = 0; it < 4; it++) {
        int cid = tid + it * 512;
        int r = cid >> 4, kc = cid & 15;
        float4 v0 = *(float4*)(sm + GOFF_AHI + (uint32_t)r * 528 + kc * 32);
        float4 v1 = *(float4*)(sm + GOFF_AHI + (uint32_t)r * 528 + kc * 32 + 16);
        int c = kc * 8;
        v0.x = fmaxf(v0.x + bs[c + 0], 0.f);
        v0.y = fmaxf(v0.y + bs[c + 1], 0.f);
        v0.z = fmaxf(v0.z + bs[c + 2], 0.f);
        v0.w = fmaxf(v0.w + bs[c + 3], 0.f);
        v1.x = fmaxf(v1.x + bs[c + 4], 0.f);
        v1.y = fmaxf(v1.y + bs[c + 5], 0.f);
        v1.z = fmaxf(v1.z + bs[c + 6], 0.f);
        v1.w = fmaxf(v1.w + bs[c + 7], 0.f);
        size_t nrow = (size_t)(n0 + r);
        if (do_next) {
            uint32_t h0, l0, h1, l1, h2, l2, h3, l3;
            split2(v0.x, v0.y, h0, l0);
            split2(v0.z, v0.w, h1, l1);
            split2(v1.x, v1.y, h2, l2);
            split2(v1.z, v1.w, h3, l3);
            chi[it] = make_uint4(h0, h1, h2, h3);
            clo[it] = make_uint4(l0, l1, l2, l3);
            ((uint4*)g_xhi)[nrow * 16 + kc] = chi[it];
            ((uint4*)g_xlo)[nrow * 16 + kc] = clo[it];
        } else {
            ((float4*)(g_x0 + nrow * 128))[kc * 2] = v0;
            ((float4*)(g_x0 + nrow * 128))[kc * 2 + 1] = v1;
        }
    }
    if (!do_next) return;
    __syncthreads();
    #pragma unroll
    for (int it = 0; it < 4; it++) {
        int cid = tid + it * 512;
        int r = cid >> 4, kc = cid & 15;
        uint32_t o = (uint32_t)r * 272 + kc * 16;
        *(uint4*)(sm + GOFF_AHI + o) = chi[it];
        *(uint4*)(sm + GOFF_ALO + o) = clo[it];
    }
    __syncthreads();

    const uint2* w1 = g_w1f + (layer + 1) * 8192;
    #pragma unroll
    for (int half = 0; half < 2; half++) {
        ACC_ZERO(acc)
        mma2_gf(sbase, GOFF_AHI, GOFF_ALO, w1,
                32, half * 16 + (wid >> 2) * 4, 0, lane, wid & 3, acc);
        write_frag_out(half == 0 ? g_xa : g_xb, n0, lane, wid & 3, wid >> 2,
                       half == 0 ? b1s : (const float*)nullptr, acc);
    }
}

// ------------------- HMMA edge kernel (PDL) -------------------
#define EOFF_ROWS 0
#define EOFF_COLS 512
#define EOFF_DIST 1024
#define EOFF_BIAS 1536
#define EOFF_W1C  2048
#define EOFF_SEG  2560
#define EOFF_AHI  4096
#define E_ASZ     34816
#define EOFF_ALO  (EOFF_AHI + E_ASZ)
#define E_SMEM    (EOFF_ALO + E_ASZ)   // 73728 -> occupancy 2

__global__ void __launch_bounds__(512, 2)
k_edge_mma(const float* __restrict__ w1c, const float* __restrict__ b2, int layer) {
    gdc_launch_dependents();   // update(l) may dispatch behind us
    extern __shared__ __align__(16) char sm[];
    uint32_t sbase = smem_u32(sm);
    int tid = threadIdx.x;
    int lane = tid & 31;
    int wid = tid >> 5;
    int e0 = blockIdx.x * 128;

    int*   rows = (int*)(sm + EOFF_ROWS);
    int*   cols = (int*)(sm + EOFF_COLS);
    float* ds   = (float*)(sm + EOFF_DIST);
    float* bs   = (float*)(sm + EOFF_BIAS);
    float* ws   = (float*)(sm + EOFF_W1C);
    int*   wcnt = (int*)(sm + EOFF_SEG);
    int*   woff = wcnt + 4;
    int*   nsegp = woff + 4;
    int*   segstart = nsegp + 1;

    if (tid < 128) {
        rows[tid] = g_srow[e0 + tid];
        cols[tid] = g_scol[e0 + tid];
        ds[tid]   = g_sdist[e0 + tid];
        bs[tid]   = b2[tid];
        ws[tid]   = w1c[tid];
    }
    __syncthreads();

    #pragma unroll
    for (int it = 0; it < 4; it++) {
        int cid = tid + it * 512;
        int e = cid >> 4;
        int kc = cid & 15;
        const float4* pa = (const float4*)(g_xa + (size_t)cols[e] * 128) + kc * 2;
        const float4* pb = (const float4*)(g_xb + (size_t)rows[e] * 128) + kc * 2;
        float d = ds[e];
        float4 a0 = pa[0], a1 = pa[1];
        float4 b0 = pb[0], b1 = pb[1];
        int k0 = kc * 8;
        float v0 = fmaxf(a0.x + b0.x + d * ws[k0 + 0], 0.f);
        float v1 = fmaxf(a0.y + b0.y + d * ws[k0 + 1], 0.f);
        float v2 = fmaxf(a0.z + b0.z + d * ws[k0 + 2], 0.f);
        float v3 = fmaxf(a0.w + b0.w + d * ws[k0 + 3], 0.f);
        float v4 = fmaxf(a1.x + b1.x + d * ws[k0 + 4], 0.f);
        float v5 = fmaxf(a1.y + b1.y + d * ws[k0 + 5], 0.f);
        float v6 = fmaxf(a1.z + b1.z + d * ws[k0 + 6], 0.f);
        float v7 = fmaxf(a1.w + b1.w + d * ws[k0 + 7], 0.f);
        uint32_t h0, l0, h1, l1, h2, l2, h3, l3;
        split2(v0, v1, h0, l0);
        split2(v2, v3, h1, l1);
        split2(v4, v5, h2, l2);
        split2(v6, v7, h3, l3);
        uint32_t o = (uint32_t)e * 272 + kc * 16;
        *(uint4*)(sm + EOFF_AHI + o) = make_uint4(h0, h1, h2, h3);
        *(uint4*)(sm + EOFF_ALO + o) = make_uint4(l0, l1, l2, l3);
    }
    __syncthreads();

    float acc[2][4][4];
    ACC_ZERO(acc)
    mma2_gf(sbase, EOFF_AHI, EOFF_ALO, g_w2f + layer * 4096,
            16, (wid >> 2) * 4, 0, lane, wid & 3, acc);
    __syncthreads();
    stage_acc(sm, EOFF_AHI, lane, wid & 3, wid >> 2, acc);

    int f = 0, pre = 0;
    if (wid < 4) {
        f = (tid == 0) || (rows[tid] != rows[tid - 1]);
        unsigned m = __ballot_sync(0xffffffffu, f);
        pre = __popc(m & ((1u << lane) - 1u));
        if (lane == 0) wcnt[wid] = __popc(m);
    }
    __syncthreads();
    if (tid == 0) {
        int s = 0;
        #pragma unroll
        for (int w = 0; w < 4; w++) { woff[w] = s; s += wcnt[w]; }
        nsegp[0] = s;
        segstart[s] = 128;
    }
    __syncthreads();
    if (wid < 4 && f) segstart[woff[wid] + pre] = tid;
    __syncthreads();

    gdc_wait();   // ensure k_zero_msum finished before reds land
    int nseg = nsegp[0];
    for (int item = tid; item < nseg * 32; item += 512) {
        int s = item >> 5, c4 = item & 31;
        int rbeg = segstart[s], rend = segstart[s + 1];
        float4 bb = *(float4*)(bs + c4 * 4);
        float m0 = 0.f, m1 = 0.f, m2 = 0.f, m3 = 0.f;
        for (int r = rbeg; r < rend; r++) {
            float4 v = *(float4*)(sm + EOFF_AHI + (uint32_t)r * 528 + c4 * 16);
            m0 += fmaxf(v.x + bb.x, 0.f);
            m1 += fmaxf(v.y + bb.y, 0.f);
            m2 += fmaxf(v.z + bb.z, 0.f);
            m3 += fmaxf(v.w + bb.w, 0.f);
        }
        float* p = g_msum + (size_t)rows[rbeg] * 128 + c4 * 4;
        asm volatile("red.global.add.v4.f32 [%0], {%1,%2,%3,%4};"
                     :: "l"(p), "f"(m0), "f"(m1), "f"(m2), "f"(m3) : "memory");
    }
}

// ------------------- readout pooling (fused ligcnt) -------------------
__global__ void k_pool(const int* __restrict__ batch, const int* __restrict__ ntype) {
    int idx = blockIdx.x * blockDim.x + threadIdx.x;
    int n = idx >> 5;
    int q = idx & 31;
    if (n >= Nn) return;
    if (ntype[n] == 1) {
        int b = batch[n];
        float4 v = ((const float4*)g_x0)[n * 32 + q];
        float* p = &g_gsum[b * 128 + q * 4];
        asm volatile("red.global.add.v4.f32 [%0], {%1,%2,%3,%4};"
                     :: "l"(p), "f"(v.x), "f"(v.y), "f"(v.z), "f"(v.w) : "memory");
        if (q == 0) atomicAdd(&g_ligcnt[b], 1.f);
    }
}

__global__ void __launch_bounds__(128)
k_readout(const float* __restrict__ rw1, const float* __restrict__ rb1,
          const float* __restrict__ rw2, const float* __restrict__ rb2,
          float* __restrict__ out) {
    __shared__ __align__(16) float gs[128];
    __shared__ float red_s[128];
    int b = blockIdx.x;
    int tid = threadIdx.x;
    float cnt = fmaxf(g_ligcnt[b], 1.f);
    gs[tid] = g_gsum[b * 128 + tid] / cnt;
    g_gsum[b * 128 + tid] = 0.f;
    if (tid == 0) g_ligcnt[b] = 0.f;
    __syncthreads();

    int j = tid;
    const float* Wj = rw1 + j;
    const float4* gs4 = (const float4*)gs;
    float acc = rb1[j];
    for (int kk = 0; kk < 32; kk++) {
        float w0 = Wj[(kk * 4 + 0) * 128];
        float w1 = Wj[(kk * 4 + 1) * 128];
        float w2 = Wj[(kk * 4 + 2) * 128];
        float w3 = Wj[(kk * 4 + 3) * 128];
        float4 gv = gs4[kk];
        acc += gv.x * w0 + gv.y * w1 + gv.z * w2 + gv.w * w3;
    }
    float hg = fmaxf(acc, 0.f);
    red_s[tid] = hg * rw2[j];
    __syncthreads();
    for (int s = 64; s > 0; s >>= 1) {
        if (tid < s) red_s[tid] += red_s[tid + s];
        __syncthreads();
    }
    if (tid == 0) out[b] = red_s[0] + rb2[0];
}

// ------------------- launch -------------------
extern "C" void kernel_launch(void* const* d_in, const int* in_sizes, int n_in,
                              void* d_out, int out_size) {
    const float* pos   = (const float*)d_in[0];
    const int*   z     = (const int*)d_in[1];
    const int*   batch = (const int*)d_in[2];
    const int*   eidx  = (const int*)d_in[3];
    const int*   ntype = (const int*)d_in[4];
    const float* emb   = (const float*)d_in[5];
    const float* lin_w = (const float*)d_in[6];
    const float* lin_b = (const float*)d_in[7];
    const float* mw1   = (const float*)d_in[8];
    const float* mb1   = (const float*)d_in[9];
    const float* mw2   = (const float*)d_in[10];
    const float* mb2   = (const float*)d_in[11];
    const float* uw    = (const float*)d_in[12];
    const float* ub    = (const float*)d_in[13];
    const float* rw1   = (const float*)d_in[14];
    const float* rb1   = (const float*)d_in[15];
    const float* rw2   = (const float*)d_in[16];
    const float* rb2   = (const float*)d_in[17];
    float* out = (float*)d_out;

    cudaFuncSetAttribute(k_edge_mma, cudaFuncAttributeMaxDynamicSharedMemorySize, E_SMEM);
    cudaFuncSetAttribute(k_input_xab, cudaFuncAttributeMaxDynamicSharedMemorySize, G_SMEM);
    cudaFuncSetAttribute(k_update_xab, cudaFuncAttributeMaxDynamicSharedMemorySize, G_SMEM);

    cudaLaunchAttribute pdl[1];
    pdl[0].id = cudaLaunchAttributeProgrammaticStreamSerialization;
    pdl[0].val.programmaticStreamSerializationAllowed = 1;

    k_prep<<<256, 256>>>(mw1, mw2, uw, lin_w);
    k_center_sum<<<Nn / 256, 256>>>(pos, batch);
    k_center_fin<<<1, 64>>>();
    k_input_xab<<<Nn / 128, 512, G_SMEM>>>(pos, z, batch, emb, lin_w, lin_b, mb1);

    // k_deg overlaps k_input_xab (independent data)
    {
        cudaLaunchConfig_t dcfg = {};
        dcfg.gridDim = dim3(Ee / 256);
        dcfg.blockDim = dim3(256);
        dcfg.attrs = pdl;
        dcfg.numAttrs = 1;
        cudaLaunchKernelEx(&dcfg, k_deg, eidx);
    }
    k_scan1<<<256, 256>>>();
    k_scan2<<<1, 256>>>();
    k_scan3<<<Nn / 256, 256>>>();
    k_scatter<<<Ee / 256, 256>>>(eidx);

    for (int l = 0; l < 3; l++) {
        const float* W1 = mw1 + l * 257 * 128;

        // zero_msum: PDL consumer for l>=1 (overlaps update(l-1) tail); first one plain
        if (l == 0) {
            k_zero_msum<<<(Nn * Hh / 4) / 512, 512>>>();
        } else {
            cudaLaunchConfig_t zcfg = {};
            zcfg.gridDim = dim3((Nn * Hh / 4) / 512);
            zcfg.blockDim = dim3(512);
            zcfg.attrs = pdl;
            zcfg.numAttrs = 1;
            cudaLaunchKernelEx(&zcfg, k_zero_msum);
        }

        cudaLaunchConfig_t ecfg = {};
        ecfg.gridDim = dim3(Ee / 128);
        ecfg.blockDim = dim3(512);
        ecfg.dynamicSmemBytes = E_SMEM;
        ecfg.attrs = pdl;
        ecfg.numAttrs = 1;
        cudaLaunchKernelEx(&ecfg, k_edge_mma, W1 + 256 * 128, mb2 + l * 128, l);

        cudaLaunchConfig_t ucfg = {};
        ucfg.gridDim = dim3(Nn / 128);
        ucfg.blockDim = dim3(512);
        ucfg.dynamicSmemBytes = G_SMEM;
        ucfg.attrs = pdl;
        ucfg.numAttrs = 1;
        cudaLaunchKernelEx(&ucfg, k_update_xab, ub + l * 128, l,
                           l < 2 ? (mb1 + (l + 1) * 128) : mb1, l < 2 ? 1 : 0);
    }

    k_pool<<<Nn * 32 / 256, 256>>>(batch, ntype);
    k_readout<<<Bb, 128>>>(rw1, rb1, rw2, rb2, out);
}

// round 16
// speedup vs baseline: 1.0226x; 1.0075x over previous
#include <cuda_runtime.h>
#include <cuda_fp16.h>
#include <math.h>
#include <stdint.h>

#define Nn 65536
#define Ee 1048576
#define Bb 64
#define Hh 128

// ------------------- scratch (static device globals) -------------------
__device__ float g_csum[Bb * 4];
__device__ float g_center[Bb * 3];
__device__ float g_posrel[Nn * 3];
__device__ uint32_t g_xhi[Nn * 64];       // fp16x2-packed hi split of x
__device__ uint32_t g_xlo[Nn * 64];       // fp16x2-packed lo split (residual)
__device__ float g_xa[Nn * Hh];
__device__ float g_xb[Nn * Hh];
__device__ float g_msum[Nn * Hh];
__device__ int   g_deg[Nn];
__device__ float g_invdeg[Nn];
__device__ float g_gsum[Bb * Hh];
__device__ float g_ligcnt[Bb];
// edge sort scratch
__device__ int   g_rowstart[Nn];
__device__ int   g_rowcur[Nn];
__device__ int   g_blksum[256];
__device__ int   g_srow[Ee];
__device__ int   g_scol[Ee];
__device__ float g_sdist[Ee];
// fragment-linear weights (fp16x2 pairs per lane)
__device__ uint2 g_w1f[3 * 8192];   // W1^T 256n x 128k, NT=32
__device__ uint2 g_w2f[3 * 4096];   // W2^T 128n x 128k, NT=16
__device__ uint2 g_uf[3 * 8192];    // U^T  128n x 256k, NT=16
__device__ uint2 g_linf[4096];      // lin^T 128n x 128k, NT=16

// ------------------- helpers -------------------
__device__ __forceinline__ uint32_t smem_u32(const void* p) {
    uint32_t a;
    asm("{ .reg .u64 t; cvta.to.shared.u64 t, %1; cvt.u32.u64 %0, t; }" : "=r"(a) : "l"(p));
    return a;
}
__device__ __forceinline__ void ldsm_x4(uint32_t* r, uint32_t addr) {
    asm volatile("ldmatrix.sync.aligned.m8n8.x4.shared.b16 {%0,%1,%2,%3}, [%4];"
                 : "=r"(r[0]), "=r"(r[1]), "=r"(r[2]), "=r"(r[3]) : "r"(addr));
}
__device__ __forceinline__ void mma_f16(float* d, const uint32_t* a, const uint32_t* b) {
    asm volatile("mma.sync.aligned.m16n8k16.row.col.f32.f16.f16.f32 "
                 "{%0,%1,%2,%3}, {%4,%5,%6,%7}, {%8,%9}, {%0,%1,%2,%3};"
                 : "+f"(d[0]), "+f"(d[1]), "+f"(d[2]), "+f"(d[3])
                 : "r"(a[0]), "r"(a[1]), "r"(a[2]), "r"(a[3]), "r"(b[0]), "r"(b[1]));
}
__device__ __forceinline__ void split2(float v0, float v1, uint32_t& hi, uint32_t& lo) {
    __half2 h = __floats2half2_rn(v0, v1);
    float h0 = __half2float(__low2half(h));
    float h1 = __half2float(__high2half(h));
    __half2 l = __floats2half2_rn(v0 - h0, v1 - h1);
    hi = *(uint32_t*)&h;
    lo = *(uint32_t*)&l;
}
__device__ __forceinline__ uint32_t pack_h2(float v0, float v1) {
    __half2 h = __floats2half2_rn(v0, v1);
    return *(uint32_t*)&h;
}
// PDL primitives (sm_90+ PTX, no arch suffix)
__device__ __forceinline__ void gdc_launch_dependents() {
    asm volatile("griddepcontrol.launch_dependents;");
}
__device__ __forceinline__ void gdc_wait() {
    asm volatile("griddepcontrol.wait;" ::: "memory");
}

// 2-term MMA core: D += (Ahi + Alo) * Bhi. warp tile m32 x n32.
__device__ __forceinline__ void mma2_gf(uint32_t sbase, uint32_t oAhi, uint32_t oAlo,
                                        const uint2* __restrict__ bf,
                                        int NT, int nt_base, int ks_base,
                                        int lane, int warp_m,
                                        float (&acc)[2][4][4]) {
    uint32_t a_base = sbase + oAhi + (uint32_t)(warp_m * 32 + (lane & 15)) * 272 + (uint32_t)(lane >> 4) * 16;
    uint32_t dA = oAlo - oAhi;
    for (int ks = 0; ks < 8; ks++) {
        uint32_t kb = (uint32_t)ks * 32;
        uint32_t a_hi[2][4], a_lo[2][4];
        #pragma unroll
        for (int mt = 0; mt < 2; mt++) {
            uint32_t ad = a_base + (uint32_t)(mt * 16) * 272 + kb;
            ldsm_x4(a_hi[mt], ad);
            ldsm_x4(a_lo[mt], ad + dA);
        }
        int fks = (ks_base + ks) * NT + nt_base;
        #pragma unroll
        for (int nt = 0; nt < 4; nt++) {
            uint2 bh = __ldg(bf + (size_t)(fks + nt) * 32 + lane);
            uint32_t bhv[2] = {bh.x, bh.y};
            mma_f16(acc[0][nt], a_hi[0], bhv);
            mma_f16(acc[1][nt], a_hi[1], bhv);
            mma_f16(acc[0][nt], a_lo[0], bhv);
            mma_f16(acc[1][nt], a_lo[1], bhv);
        }
    }
}

__device__ __forceinline__ void stage_acc(char* sm, uint32_t oM, int lane, int warp_m, int warp_n,
                                          float (&acc)[2][4][4]) {
    #pragma unroll
    for (int mt = 0; mt < 2; mt++) {
        int er = warp_m * 32 + mt * 16 + (lane >> 2);
        #pragma unroll
        for (int nt = 0; nt < 4; nt++) {
            int cb = warp_n * 32 + nt * 8 + (lane & 3) * 2;
            *(float2*)(sm + oM + (uint32_t)er * 528 + cb * 4) = make_float2(acc[mt][nt][0], acc[mt][nt][1]);
            *(float2*)(sm + oM + (uint32_t)(er + 8) * 528 + cb * 4) = make_float2(acc[mt][nt][2], acc[mt][nt][3]);
        }
    }
}

__device__ __forceinline__ void write_frag_out(float* out, int n0, int lane, int warp_m, int warp_n,
                                               const float* bsm, float (&acc)[2][4][4]) {
    #pragma unroll
    for (int mt = 0; mt < 2; mt++) {
        int er = n0 + warp_m * 32 + mt * 16 + (lane >> 2);
        #pragma unroll
        for (int nt = 0; nt < 4; nt++) {
            int cb = warp_n * 32 + nt * 8 + (lane & 3) * 2;
            float b0 = bsm ? bsm[cb] : 0.f;
            float b1 = bsm ? bsm[cb + 1] : 0.f;
            *(float2*)(out + (size_t)er * 128 + cb) = make_float2(acc[mt][nt][0] + b0, acc[mt][nt][1] + b1);
            *(float2*)(out + (size_t)(er + 8) * 128 + cb) = make_float2(acc[mt][nt][2] + b0, acc[mt][nt][3] + b1);
        }
    }
}

#define ACC_ZERO(acc) \
    _Pragma("unroll") \
    for (int mt = 0; mt < 2; mt++) \
        _Pragma("unroll") \
        for (int nt = 0; nt < 4; nt++) \
            _Pragma("unroll") \
            for (int q = 0; q < 4; q++) (acc)[mt][nt][q] = 0.f;

// ------------------- small kernels -------------------
__global__ void k_center_sum(const float* __restrict__ pos, const int* __restrict__ batch) {
    int n = blockIdx.x * blockDim.x + threadIdx.x;
    if (n >= Nn) return;
    int lane = threadIdx.x & 31;
    int b = batch[n];
    float px = pos[n * 3 + 0], py = pos[n * 3 + 1], pz = pos[n * 3 + 2], pc = 1.f;
    #pragma unroll
    for (int off = 1; off < 32; off <<= 1) {
        int bs = __shfl_down_sync(0xffffffffu, b, off);
        float tx = __shfl_down_sync(0xffffffffu, px, off);
        float ty = __shfl_down_sync(0xffffffffu, py, off);
        float tz = __shfl_down_sync(0xffffffffu, pz, off);
        float tc = __shfl_down_sync(0xffffffffu, pc, off);
        if (lane + off < 32 && bs == b) { px += tx; py += ty; pz += tz; pc += tc; }
    }
    int bprev = __shfl_up_sync(0xffffffffu, b, 1);
    if (lane == 0 || bprev != b) {
        atomicAdd(&g_csum[b * 4 + 0], px);
        atomicAdd(&g_csum[b * 4 + 1], py);
        atomicAdd(&g_csum[b * 4 + 2], pz);
        atomicAdd(&g_csum[b * 4 + 3], pc);
    }
}

__global__ void k_center_fin() {
    int b = threadIdx.x;
    if (b < Bb) {
        float c = fmaxf(g_csum[b * 4 + 3], 1.f);
        g_center[b * 3 + 0] = g_csum[b * 4 + 0] / c;
        g_center[b * 3 + 1] = g_csum[b * 4 + 1] / c;
        g_center[b * 3 + 2] = g_csum[b * 4 + 2] / c;
        g_csum[b * 4 + 0] = 0.f;
        g_csum[b * 4 + 1] = 0.f;
        g_csum[b * 4 + 2] = 0.f;
        g_csum[b * 4 + 3] = 0.f;
    }
}

__global__ void k_deg(const int* __restrict__ eidx) {
    int e = blockIdx.x * blockDim.x + threadIdx.x;
    if (e < Ee) atomicAdd(&g_deg[eidx[e]], 1);
}

// ------------------- counting sort -------------------
__global__ void k_scan1() {
    __shared__ int s[256];
    int i = blockIdx.x * 256 + threadIdx.x;
    int v = g_deg[i];
    s[threadIdx.x] = v;
    __syncthreads();
    for (int off = 1; off < 256; off <<= 1) {
        int t = (threadIdx.x >= off) ? s[threadIdx.x - off] : 0;
        __syncthreads();
        s[threadIdx.x] += t;
        __syncthreads();
    }
    g_rowstart[i] = s[threadIdx.x] - v;
    if (threadIdx.x == 255) g_blksum[blockIdx.x] = s[255];
}
__global__ void k_scan2() {
    __shared__ int s[256];
    int i = threadIdx.x;
    int v = g_blksum[i];
    s[i] = v;
    __syncthreads();
    for (int off = 1; off < 256; off <<= 1) {
        int t = (i >= off) ? s[i - off] : 0;
        __syncthreads();
        s[i] += t;
        __syncthreads();
    }
    g_blksum[i] = s[i] - v;
}
__global__ void k_scan3() {
    int i = blockIdx.x * blockDim.x + threadIdx.x;
    if (i < Nn) {
        int v = g_rowstart[i] + g_blksum[i >> 8];
        g_rowstart[i] = v;
        g_rowcur[i] = v;
        g_invdeg[i] = 1.f / fmaxf((float)g_deg[i], 1.f);
        g_deg[i] = 0;
    }
}
__global__ void k_scatter(const int* __restrict__ eidx) {
    int e = blockIdx.x * blockDim.x + threadIdx.x;
    if (e >= Ee) return;
    int r = eidx[e], c = eidx[Ee + e];
    int p = atomicAdd(&g_rowcur[r], 1);
    float dx = g_posrel[c * 3 + 0] - g_posrel[r * 3 + 0];
    float dy = g_posrel[c * 3 + 1] - g_posrel[r * 3 + 1];
    float dz = g_posrel[c * 3 + 2] - g_posrel[r * 3 + 2];
    g_srow[p] = r;
    g_scol[p] = c;
    g_sdist[p] = sqrtf(dx * dx + dy * dy + dz * dz);
}

// ------------------- msum zeroing (PDL: waits for update's pass-1 reads, fires edge) --
__global__ void k_zero_msum() {
    gdc_wait();
    gdc_launch_dependents();
    int i = blockIdx.x * blockDim.x + threadIdx.x;
    ((float4*)g_msum)[i] = make_float4(0.f, 0.f, 0.f, 0.f);
}

// ------------------- combined weight prep (fires PDL so center_sum overlaps) ----------
__global__ void k_prep(const float* __restrict__ mw1, const float* __restrict__ mw2,
                       const float* __restrict__ uw, const float* __restrict__ lin_w) {
    gdc_launch_dependents();   // k_center_sum is independent; let it overlap us
    int idx = blockIdx.x * blockDim.x + threadIdx.x;
    if (idx < 24576) {
        int l = idx / 8192, r = idx % 8192;
        int ks = r >> 10, ntile = (r >> 5) & 31, lane = r & 31;
        int n = ntile * 8 + (lane >> 2);
        int k0 = ks * 16 + (lane & 3) * 2;
        const float* W = mw1 + l * 257 * 128;
        float v[4];
        #pragma unroll
        for (int q = 0; q < 4; q++) {
            int k = k0 + (q >> 1) * 8 + (q & 1);
            v[q] = (n < 128) ? W[k * 128 + n] : W[(128 + k) * 128 + (n - 128)];
        }
        g_w1f[idx] = make_uint2(pack_h2(v[0], v[1]), pack_h2(v[2], v[3]));
    } else if (idx < 36864) {
        int i = idx - 24576;
        int l = i / 4096, r = i % 4096;
        int ks = r >> 9, ntile = (r >> 5) & 15, lane = r & 31;
        int n = ntile * 8 + (lane >> 2);
        int k0 = ks * 16 + (lane & 3) * 2;
        const float* W = mw2 + l * 16384;
        float v[4];
        #pragma unroll
        for (int q = 0; q < 4; q++) {
            int k = k0 + (q >> 1) * 8 + (q & 1);
            v[q] = W[k * 128 + n];
        }
        g_w2f[i] = make_uint2(pack_h2(v[0], v[1]), pack_h2(v[2], v[3]));
    } else if (idx < 61440) {
        int i = idx - 36864;
        int l = i / 8192, r = i % 8192;
        int ks = r >> 9, ntile = (r >> 5) & 15, lane = r & 31;
        int n = ntile * 8 + (lane >> 2);
        int k0 = ks * 16 + (lane & 3) * 2;
        const float* W = uw + l * 32768;
        float v[4];
        #pragma unroll
        for (int q = 0; q < 4; q++) {
            int k = k0 + (q >> 1) * 8 + (q & 1);
            v[q] = W[k * 128 + n];
        }
        g_uf[i] = make_uint2(pack_h2(v[0], v[1]), pack_h2(v[2], v[3]));
    } else {
        int i = idx - 61440;
        int ks = i >> 9, ntile = (i >> 5) & 15, lane = i & 31;
        int n = ntile * 8 + (lane >> 2);
        int k0 = ks * 16 + (lane & 3) * 2;
        float v[4];
        #pragma unroll
        for (int q = 0; q < 4; q++) {
            int k = k0 + (q >> 1) * 8 + (q & 1);
            v[q] = lin_w[k * 128 + n];
        }
        g_linf[i] = make_uint2(pack_h2(v[0], v[1]), pack_h2(v[2], v[3]));
    }
}

// ------------------- node-kernel smem layout -------------------
#define GOFF_BIAS 0
#define GOFF_AUX  512
#define GOFF_IDX  2048
#define GOFF_B1   4096
#define GOFF_AHI  4608
#define G_ASZ     34816
#define GOFF_ALO  (GOFF_AHI + G_ASZ)
#define G_SMEM    (GOFF_ALO + G_ASZ)   // 74240 -> occupancy 2

// ------------------- k_input_xab (fires PDL for k_deg at entry) -------------------
__global__ void __launch_bounds__(512, 2)
k_input_xab(const float* __restrict__ pos, const int* __restrict__ z,
            const int* __restrict__ batch, const float* __restrict__ emb,
            const float* __restrict__ lin_w, const float* __restrict__ bias,
            const float* __restrict__ b1n) {
    gdc_launch_dependents();
    extern __shared__ __align__(16) char sm[];
    uint32_t sbase = smem_u32(sm);
    int tid = threadIdx.x;
    int lane = tid & 31;
    int wid = tid >> 5;
    int n0 = blockIdx.x * 128;
    float* bs  = (float*)(sm + GOFF_BIAS);
    float* tl  = (float*)(sm + GOFF_AUX);
    float* prs = (float*)(sm + GOFF_IDX);
    int*   zs  = (int*)(sm + GOFF_IDX + 1536);
    float* b1s = (float*)(sm + GOFF_B1);

    if (tid < 128) {
        bs[tid] = bias[tid];
        b1s[tid] = b1n[tid];
        int n = n0 + tid;
        int b = batch[n];
        #pragma unroll
        for (int d = 0; d < 3; d++) {
            float v = pos[n * 3 + d] - g_center[b * 3 + d];
            prs[tid * 3 + d] = v;
            g_posrel[n * 3 + d] = v;
        }
        zs[tid] = z[n];
    } else if (tid >= 128 && tid < 128 + 384) {
        int i = tid - 128;
        tl[i] = lin_w[(128 + (i >> 7)) * 128 + (i & 127)];
    }
    __syncthreads();

    #pragma unroll
    for (int it = 0; it < 4; it++) {
        int cid = tid + it * 512;
        int r = cid >> 4, kc = cid & 15;
        const float4* ep = (const float4*)(emb + (size_t)zs[r] * 128) + kc * 2;
        float4 e0 = ep[0], e1 = ep[1];
        uint32_t h0, l0, h1, l1, h2, l2, h3, l3;
        split2(e0.x, e0.y, h0, l0);
        split2(e0.z, e0.w, h1, l1);
        split2(e1.x, e1.y, h2, l2);
        split2(e1.z, e1.w, h3, l3);
        uint32_t o = (uint32_t)r * 272 + kc * 16;
        *(uint4*)(sm + GOFF_AHI + o) = make_uint4(h0, h1, h2, h3);
        *(uint4*)(sm + GOFF_ALO + o) = make_uint4(l0, l1, l2, l3);
    }
    __syncthreads();

    float acc[2][4][4];
    ACC_ZERO(acc)
    mma2_gf(sbase, GOFF_AHI, GOFF_ALO, g_linf, 16, (wid >> 2) * 4, 0, lane, wid & 3, acc);
    __syncthreads();
    stage_acc(sm, GOFF_AHI, lane, wid & 3, wid >> 2, acc);
    __syncthreads();

    uint4 chi[4], clo[4];
    #pragma unroll
    for (int it = 0; it < 4; it++) {
        int cid = tid + it * 512;
        int r = cid >> 4, kc = cid & 15;
        float4 v0 = *(float4*)(sm + GOFF_AHI + (uint32_t)r * 528 + kc * 32);
        float4 v1 = *(float4*)(sm + GOFF_AHI + (uint32_t)r * 528 + kc * 32 + 16);
        float p0 = prs[r * 3 + 0], p1 = prs[r * 3 + 1], p2 = prs[r * 3 + 2];
        int c = kc * 8;
        v0.x += bs[c + 0] + p0 * tl[c + 0] + p1 * tl[128 + c + 0] + p2 * tl[256 + c + 0];
        v0.y += bs[c + 1] + p0 * tl[c + 1] + p1 * tl[128 + c + 1] + p2 * tl[256 + c + 1];
        v0.z += bs[c + 2] + p0 * tl[c + 2] + p1 * tl[128 + c + 2] + p2 * tl[256 + c + 2];
        v0.w += bs[c + 3] + p0 * tl[c + 3] + p1 * tl[128 + c + 3] + p2 * tl[256 + c + 3];
        v1.x += bs[c + 4] + p0 * tl[c + 4] + p1 * tl[128 + c + 4] + p2 * tl[256 + c + 4];
        v1.y += bs[c + 5] + p0 * tl[c + 5] + p1 * tl[128 + c + 5] + p2 * tl[256 + c + 5];
        v1.z += bs[c + 6] + p0 * tl[c + 6] + p1 * tl[128 + c + 6] + p2 * tl[256 + c + 6];
        v1.w += bs[c + 7] + p0 * tl[c + 7] + p1 * tl[128 + c + 7] + p2 * tl[256 + c + 7];
        uint32_t h0, l0, h1, l1, h2, l2, h3, l3;
        split2(v0.x, v0.y, h0, l0);
        split2(v0.z, v0.w, h1, l1);
        split2(v1.x, v1.y, h2, l2);
        split2(v1.z, v1.w, h3, l3);
        chi[it] = make_uint4(h0, h1, h2, h3);
        clo[it] = make_uint4(l0, l1, l2, l3);
        size_t nrow = (size_t)(n0 + r);
        ((uint4*)g_xhi)[nrow * 16 + kc] = chi[it];
        ((uint4*)g_xlo)[nrow * 16 + kc] = clo[it];
    }
    __syncthreads();
    #pragma unroll
    for (int it = 0; it < 4; it++) {
        int cid = tid + it * 512;
        int r = cid >> 4, kc = cid & 15;
        uint32_t o = (uint32_t)r * 272 + kc * 16;
        *(uint4*)(sm + GOFF_AHI + o) = chi[it];
        *(uint4*)(sm + GOFF_ALO + o) = clo[it];
    }
    __syncthreads();

    #pragma unroll
    for (int half = 0; half < 2; half++) {
        ACC_ZERO(acc)
        mma2_gf(sbase, GOFF_AHI, GOFF_ALO, g_w1f,
                32, half * 16 + (wid >> 2) * 4, 0, lane, wid & 3, acc);
        write_frag_out(half == 0 ? g_xa : g_xb, n0, lane, wid & 3, wid >> 2,
                       half == 0 ? b1s : (const float*)nullptr, acc);
    }
}

// ------------------- k_update_xab (fused pool on last layer; PDL) ---------------------
__global__ void __launch_bounds__(512, 2)
k_update_xab(const float* __restrict__ bias, int layer,
             const float* __restrict__ b1n, int do_next,
             const int* __restrict__ batch, const int* __restrict__ ntype) {
    extern __shared__ __align__(16) char sm[];
    uint32_t sbase = smem_u32(sm);
    int tid = threadIdx.x;
    int lane = tid & 31;
    int wid = tid >> 5;
    int n0 = blockIdx.x * 128;
    float* bs = (float*)(sm + GOFF_BIAS);
    float* idg = (float*)(sm + GOFF_AUX);
    float* b1s = (float*)(sm + GOFF_B1);
    int* bts = (int*)(sm + GOFF_IDX);          // 128 ints (batch)
    int* ntp = (int*)(sm + GOFF_IDX + 512);    // 128 ints (ntype)
    if (tid < 128) {
        bs[tid] = bias[tid];
        idg[tid] = g_invdeg[n0 + tid];
        b1s[tid] = do_next ? b1n[tid] : 0.f;
        if (!do_next) {
            bts[tid] = batch[n0 + tid];
            ntp[tid] = ntype[n0 + tid];
        }
    }

    const uint2* uf = g_uf + layer * 8192;

    float acc[2][4][4];
    ACC_ZERO(acc)

    // pass 0: A = x hi/lo
    {
        const uint4* ah = (const uint4*)g_xhi + (size_t)n0 * 16;
        const uint4* al = (const uint4*)g_xlo + (size_t)n0 * 16;
        #pragma unroll
        for (int it = 0; it < 4; it++) {
            int cid = tid + it * 512;
            int r = cid >> 4, c = cid & 15;
            uint32_t o = (uint32_t)r * 272 + c * 16;
            *(uint4*)(sm + GOFF_AHI + o) = ah[r * 16 + c];
            *(uint4*)(sm + GOFF_ALO + o) = al[r * 16 + c];
        }
        __syncthreads();
        mma2_gf(sbase, GOFF_AHI, GOFF_ALO, uf, 16, (wid >> 2) * 4, 0, lane, wid & 3, acc);
        __syncthreads();
    }
    // pass 1: wait for edge, consume msum, fire next zeroing
    gdc_wait();
    {
        #pragma unroll
        for (int it = 0; it < 4; it++) {
            int cid = tid + it * 512;
            int r = cid >> 4, c = cid & 15;
            uint32_t o = (uint32_t)r * 272 + c * 16;
            const float4* mp = (const float4*)(g_msum + (size_t)(n0 + r) * 128) + c * 2;
            float s = idg[r];
            float4 m0 = mp[0], m1 = mp[1];
            uint32_t h0, l0, h1, l1, h2, l2, h3, l3;
            split2(m0.x * s, m0.y * s, h0, l0);
            split2(m0.z * s, m0.w * s, h1, l1);
            split2(m1.x * s, m1.y * s, h2, l2);
            split2(m1.z * s, m1.w * s, h3, l3);
            *(uint4*)(sm + GOFF_AHI + o) = make_uint4(h0, h1, h2, h3);
            *(uint4*)(sm + GOFF_ALO + o) = make_uint4(l0, l1, l2, l3);
        }
        __syncthreads();
        gdc_launch_dependents();
        mma2_gf(sbase, GOFF_AHI, GOFF_ALO, uf, 16, (wid >> 2) * 4, 8, lane, wid & 3, acc);
        __syncthreads();
    }

    stage_acc(sm, GOFF_AHI, lane, wid & 3, wid >> 2, acc);
    __syncthreads();

    uint4 chi[4], clo[4];
    #pragma unroll
    for (int it = 0; it < 4; it++) {
        int cid = tid + it * 512;
        int r = cid >> 4, kc = cid & 15;
        float4 v0 = *(float4*)(sm + GOFF_AHI + (uint32_t)r * 528 + kc * 32);
        float4 v1 = *(float4*)(sm + GOFF_AHI + (uint32_t)r * 528 + kc * 32 + 16);
        int c = kc * 8;
        v0.x = fmaxf(v0.x + bs[c + 0], 0.f);
        v0.y = fmaxf(v0.y + bs[c + 1], 0.f);
        v0.z = fmaxf(v0.z + bs[c + 2], 0.f);
        v0.w = fmaxf(v0.w + bs[c + 3], 0.f);
        v1.x = fmaxf(v1.x + bs[c + 4], 0.f);
        v1.y = fmaxf(v1.y + bs[c + 5], 0.f);
        v1.z = fmaxf(v1.z + bs[c + 6], 0.f);
        v1.w = fmaxf(v1.w + bs[c + 7], 0.f);
        size_t nrow = (size_t)(n0 + r);
        if (do_next) {
            uint32_t h0, l0, h1, l1, h2, l2, h3, l3;
            split2(v0.x, v0.y, h0, l0);
            split2(v0.z, v0.w, h1, l1);
            split2(v1.x, v1.y, h2, l2);
            split2(v1.z, v1.w, h3, l3);
            chi[it] = make_uint4(h0, h1, h2, h3);
            clo[it] = make_uint4(l0, l1, l2, l3);
            ((uint4*)g_xhi)[nrow * 16 + kc] = chi[it];
            ((uint4*)g_xlo)[nrow * 16 + kc] = clo[it];
        } else {
            // fused pooling: red straight into g_gsum for ligand nodes
            if (ntp[r] == 1) {
                int b = bts[r];
                float* p = &g_gsum[b * 128 + c];
                asm volatile("red.global.add.v4.f32 [%0], {%1,%2,%3,%4};"
                             :: "l"(p), "f"(v0.x), "f"(v0.y), "f"(v0.z), "f"(v0.w) : "memory");
                asm volatile("red.global.add.v4.f32 [%0], {%1,%2,%3,%4};"
                             :: "l"(p + 4), "f"(v1.x), "f"(v1.y), "f"(v1.z), "f"(v1.w) : "memory");
                if (kc == 0) atomicAdd(&g_ligcnt[b], 1.f);
            }
        }
    }
    if (!do_next) return;
    __syncthreads();
    #pragma unroll
    for (int it = 0; it < 4; it++) {
        int cid = tid + it * 512;
        int r = cid >> 4, kc = cid & 15;
        uint32_t o = (uint32_t)r * 272 + kc * 16;
        *(uint4*)(sm + GOFF_AHI + o) = chi[it];
        *(uint4*)(sm + GOFF_ALO + o) = clo[it];
    }
    __syncthreads();

    const uint2* w1 = g_w1f + (layer + 1) * 8192;
    #pragma unroll
    for (int half = 0; half < 2; half++) {
        ACC_ZERO(acc)
        mma2_gf(sbase, GOFF_AHI, GOFF_ALO, w1,
                32, half * 16 + (wid >> 2) * 4, 0, lane, wid & 3, acc);
        write_frag_out(half == 0 ? g_xa : g_xb, n0, lane, wid & 3, wid >> 2,
                       half == 0 ? b1s : (const float*)nullptr, acc);
    }
}

// ------------------- HMMA edge kernel (PDL) -------------------
#define EOFF_ROWS 0
#define EOFF_COLS 512
#define EOFF_DIST 1024
#define EOFF_BIAS 1536
#define EOFF_W1C  2048
#define EOFF_SEG  2560
#define EOFF_AHI  4096
#define E_ASZ     34816
#define EOFF_ALO  (EOFF_AHI + E_ASZ)
#define E_SMEM    (EOFF_ALO + E_ASZ)   // 73728 -> occupancy 2

__global__ void __launch_bounds__(512, 2)
k_edge_mma(const float* __restrict__ w1c, const float* __restrict__ b2, int layer) {
    gdc_launch_dependents();
    extern __shared__ __align__(16) char sm[];
    uint32_t sbase = smem_u32(sm);
    int tid = threadIdx.x;
    int lane = tid & 31;
    int wid = tid >> 5;
    int e0 = blockIdx.x * 128;

    int*   rows = (int*)(sm + EOFF_ROWS);
    int*   cols = (int*)(sm + EOFF_COLS);
    float* ds   = (float*)(sm + EOFF_DIST);
    float* bs   = (float*)(sm + EOFF_BIAS);
    float* ws   = (float*)(sm + EOFF_W1C);
    int*   wcnt = (int*)(sm + EOFF_SEG);
    int*   woff = wcnt + 4;
    int*   nsegp = woff + 4;
    int*   segstart = nsegp + 1;

    if (tid < 128) {
        rows[tid] = g_srow[e0 + tid];
        cols[tid] = g_scol[e0 + tid];
        ds[tid]   = g_sdist[e0 + tid];
        bs[tid]   = b2[tid];
        ws[tid]   = w1c[tid];
    }
    __syncthreads();

    #pragma unroll
    for (int it = 0; it < 4; it++) {
        int cid = tid + it * 512;
        int e = cid >> 4;
        int kc = cid & 15;
        const float4* pa = (const float4*)(g_xa + (size_t)cols[e] * 128) + kc * 2;
        const float4* pb = (const float4*)(g_xb + (size_t)rows[e] * 128) + kc * 2;
        float d = ds[e];
        float4 a0 = pa[0], a1 = pa[1];
        float4 b0 = pb[0], b1 = pb[1];
        int k0 = kc * 8;
        float v0 = fmaxf(a0.x + b0.x + d * ws[k0 + 0], 0.f);
        float v1 = fmaxf(a0.y + b0.y + d * ws[k0 + 1], 0.f);
        float v2 = fmaxf(a0.z + b0.z + d * ws[k0 + 2], 0.f);
        float v3 = fmaxf(a0.w + b0.w + d * ws[k0 + 3], 0.f);
        float v4 = fmaxf(a1.x + b1.x + d * ws[k0 + 4], 0.f);
        float v5 = fmaxf(a1.y + b1.y + d * ws[k0 + 5], 0.f);
        float v6 = fmaxf(a1.z + b1.z + d * ws[k0 + 6], 0.f);
        float v7 = fmaxf(a1.w + b1.w + d * ws[k0 + 7], 0.f);
        uint32_t h0, l0, h1, l1, h2, l2, h3, l3;
        split2(v0, v1, h0, l0);
        split2(v2, v3, h1, l1);
        split2(v4, v5, h2, l2);
        split2(v6, v7, h3, l3);
        uint32_t o = (uint32_t)e * 272 + kc * 16;
        *(uint4*)(sm + EOFF_AHI + o) = make_uint4(h0, h1, h2, h3);
        *(uint4*)(sm + EOFF_ALO + o) = make_uint4(l0, l1, l2, l3);
    }
    __syncthreads();

    float acc[2][4][4];
    ACC_ZERO(acc)
    mma2_gf(sbase, EOFF_AHI, EOFF_ALO, g_w2f + layer * 4096,
            16, (wid >> 2) * 4, 0, lane, wid & 3, acc);
    __syncthreads();
    stage_acc(sm, EOFF_AHI, lane, wid & 3, wid >> 2, acc);

    int f = 0, pre = 0;
    if (wid < 4) {
        f = (tid == 0) || (rows[tid] != rows[tid - 1]);
        unsigned m = __ballot_sync(0xffffffffu, f);
        pre = __popc(m & ((1u << lane) - 1u));
        if (lane == 0) wcnt[wid] = __popc(m);
    }
    __syncthreads();
    if (tid == 0) {
        int s = 0;
        #pragma unroll
        for (int w = 0; w < 4; w++) { woff[w] = s; s += wcnt[w]; }
        nsegp[0] = s;
        segstart[s] = 128;
    }
    __syncthreads();
    if (wid < 4 && f) segstart[woff[wid] + pre] = tid;
    __syncthreads();

    gdc_wait();
    int nseg = nsegp[0];
    for (int item = tid; item < nseg * 32; item += 512) {
        int s = item >> 5, c4 = item & 31;
        int rbeg = segstart[s], rend = segstart[s + 1];
        float4 bb = *(float4*)(bs + c4 * 4);
        float m0 = 0.f, m1 = 0.f, m2 = 0.f, m3 = 0.f;
        for (int r = rbeg; r < rend; r++) {
            float4 v = *(float4*)(sm + EOFF_AHI + (uint32_t)r * 528 + c4 * 16);
            m0 += fmaxf(v.x + bb.x, 0.f);
            m1 += fmaxf(v.y + bb.y, 0.f);
            m2 += fmaxf(v.z + bb.z, 0.f);
            m3 += fmaxf(v.w + bb.w, 0.f);
        }
        float* p = g_msum + (size_t)rows[rbeg] * 128 + c4 * 4;
        asm volatile("red.global.add.v4.f32 [%0], {%1,%2,%3,%4};"
                     :: "l"(p), "f"(m0), "f"(m1), "f"(m2), "f"(m3) : "memory");
    }
}

// ------------------- readout -------------------
__global__ void __launch_bounds__(128)
k_readout(const float* __restrict__ rw1, const float* __restrict__ rb1,
          const float* __restrict__ rw2, const float* __restrict__ rb2,
          float* __restrict__ out) {
    __shared__ __align__(16) float gs[128];
    __shared__ float red_s[128];
    int b = blockIdx.x;
    int tid = threadIdx.x;
    float cnt = fmaxf(g_ligcnt[b], 1.f);
    gs[tid] = g_gsum[b * 128 + tid] / cnt;
    g_gsum[b * 128 + tid] = 0.f;
    if (tid == 0) g_ligcnt[b] = 0.f;
    __syncthreads();

    int j = tid;
    const float* Wj = rw1 + j;
    const float4* gs4 = (const float4*)gs;
    float acc = rb1[j];
    for (int kk = 0; kk < 32; kk++) {
        float w0 = Wj[(kk * 4 + 0) * 128];
        float w1 = Wj[(kk * 4 + 1) * 128];
        float w2 = Wj[(kk * 4 + 2) * 128];
        float w3 = Wj[(kk * 4 + 3) * 128];
        float4 gv = gs4[kk];
        acc += gv.x * w0 + gv.y * w1 + gv.z * w2 + gv.w * w3;
    }
    float hg = fmaxf(acc, 0.f);
    red_s[tid] = hg * rw2[j];
    __syncthreads();
    for (int s = 64; s > 0; s >>= 1) {
        if (tid < s) red_s[tid] += red_s[tid + s];
        __syncthreads();
    }
    if (tid == 0) out[b] = red_s[0] + rb2[0];
}

// ------------------- launch -------------------
extern "C" void kernel_launch(void* const* d_in, const int* in_sizes, int n_in,
                              void* d_out, int out_size) {
    const float* pos   = (const float*)d_in[0];
    const int*   z     = (const int*)d_in[1];
    const int*   batch = (const int*)d_in[2];
    const int*   eidx  = (const int*)d_in[3];
    const int*   ntype = (const int*)d_in[4];
    const float* emb   = (const float*)d_in[5];
    const float* lin_w = (const float*)d_in[6];
    const float* lin_b = (const float*)d_in[7];
    const float* mw1   = (const float*)d_in[8];
    const float* mb1   = (const float*)d_in[9];
    const float* mw2   = (const float*)d_in[10];
    const float* mb2   = (const float*)d_in[11];
    const float* uw    = (const float*)d_in[12];
    const float* ub    = (const float*)d_in[13];
    const float* rw1   = (const float*)d_in[14];
    const float* rb1   = (const float*)d_in[15];
    const float* rw2   = (const float*)d_in[16];
    const float* rb2   = (const float*)d_in[17];
    float* out = (float*)d_out;

    cudaFuncSetAttribute(k_edge_mma, cudaFuncAttributeMaxDynamicSharedMemorySize, E_SMEM);
    cudaFuncSetAttribute(k_input_xab, cudaFuncAttributeMaxDynamicSharedMemorySize, G_SMEM);
    cudaFuncSetAttribute(k_update_xab, cudaFuncAttributeMaxDynamicSharedMemorySize, G_SMEM);

    cudaLaunchAttribute pdl[1];
    pdl[0].id = cudaLaunchAttributeProgrammaticStreamSerialization;
    pdl[0].val.programmaticStreamSerializationAllowed = 1;

    k_prep<<<256, 256>>>(mw1, mw2, uw, lin_w);
    // center_sum overlaps prep (independent data)
    {
        cudaLaunchConfig_t ccfg = {};
        ccfg.gridDim = dim3(Nn / 256);
        ccfg.blockDim = dim3(256);
        ccfg.attrs = pdl;
        ccfg.numAttrs = 1;
        cudaLaunchKernelEx(&ccfg, k_center_sum, pos, batch);
    }
    k_center_fin<<<1, 64>>>();
    k_input_xab<<<Nn / 128, 512, G_SMEM>>>(pos, z, batch, emb, lin_w, lin_b, mb1);

    // k_deg overlaps k_input_xab (independent data)
    {
        cudaLaunchConfig_t dcfg = {};
        dcfg.gridDim = dim3(Ee / 256);
        dcfg.blockDim = dim3(256);
        dcfg.attrs = pdl;
        dcfg.numAttrs = 1;
        cudaLaunchKernelEx(&dcfg, k_deg, eidx);
    }
    k_scan1<<<256, 256>>>();
    k_scan2<<<1, 256>>>();
    k_scan3<<<Nn / 256, 256>>>();
    k_scatter<<<Ee / 256, 256>>>(eidx);

    for (int l = 0; l < 3; l++) {
        const float* W1 = mw1 + l * 257 * 128;

        if (l == 0) {
            k_zero_msum<<<(Nn * Hh / 4) / 512, 512>>>();
        } else {
            cudaLaunchConfig_t zcfg = {};
            zcfg.gridDim = dim3((Nn * Hh / 4) / 512);
            zcfg.blockDim = dim3(512);
            zcfg.attrs = pdl;
            zcfg.numAttrs = 1;
            cudaLaunchKernelEx(&zcfg, k_zero_msum);
        }

        cudaLaunchConfig_t ecfg = {};
        ecfg.gridDim = dim3(Ee / 128);
        ecfg.blockDim = dim3(512);
        ecfg.dynamicSmemBytes = E_SMEM;
        ecfg.attrs = pdl;
        ecfg.numAttrs = 1;
        cudaLaunchKernelEx(&ecfg, k_edge_mma, W1 + 256 * 128, mb2 + l * 128, l);

        cudaLaunchConfig_t ucfg = {};
        ucfg.gridDim = dim3(Nn / 128);
        ucfg.blockDim = dim3(512);
        ucfg.dynamicSmemBytes = G_SMEM;
        ucfg.attrs = pdl;
        ucfg.numAttrs = 1;
        cudaLaunchKernelEx(&ucfg, k_update_xab, ub + l * 128, l,
                           l < 2 ? (mb1 + (l + 1) * 128) : mb1, l < 2 ? 1 : 0,
                           batch, ntype);
    }

    k_readout<<<Bb, 128>>>(rw1, rb1, rw2, rb2, out);
}